// round 6
// baseline (speedup 1.0000x reference)
#include <cuda_runtime.h>
#include <cuda_bf16.h>
#include <cstdint>
#include <cstdio>

// ---------------------------------------------------------------------------
// Problem constants
// ---------------------------------------------------------------------------
#define NUM_HEADS 24
#define HEAD_DIM  128
#define HIDDEN    3072
#define MLPD      12288
#define T_IMG     1536
#define T_TXT     512
#define SEQ_L     2048   // T_IMG + T_TXT

// ---------------------------------------------------------------------------
// Scratch (device globals; allocation-free per harness rules)
// ---------------------------------------------------------------------------
__device__ float g_xm[(size_t)T_IMG * HIDDEN];
__device__ float g_qkv_img[(size_t)T_IMG * 3 * HIDDEN];
__device__ float g_qkv_txt[(size_t)T_TXT * 3 * HIDDEN];
__device__ float g_q[(size_t)NUM_HEADS * SEQ_L * HEAD_DIM];
__device__ float g_k[(size_t)NUM_HEADS * SEQ_L * HEAD_DIM];
__device__ float g_vT[(size_t)NUM_HEADS * HEAD_DIM * SEQ_L];
__device__ float g_scores[(size_t)NUM_HEADS * SEQ_L * SEQ_L];   // ~402 MB
__device__ float g_attn[(size_t)SEQ_L * HIDDEN];
__device__ float g_tmp[(size_t)T_IMG * HIDDEN];
__device__ float g_h[(size_t)T_IMG * MLPD];

// ---------------------------------------------------------------------------
// Helpers
// ---------------------------------------------------------------------------
__device__ __forceinline__ void mma_tf32(float* d, const uint32_t* a, const uint32_t* b) {
    asm volatile(
        "mma.sync.aligned.m16n8k8.row.col.f32.tf32.tf32.f32 "
        "{%0,%1,%2,%3}, {%4,%5,%6,%7}, {%8,%9}, {%0,%1,%2,%3};\n"
        : "+f"(d[0]), "+f"(d[1]), "+f"(d[2]), "+f"(d[3])
        : "r"(a[0]), "r"(a[1]), "r"(a[2]), "r"(a[3]), "r"(b[0]), "r"(b[1]));
}

__device__ __forceinline__ void cp_async16(uint32_t saddr, const float* gaddr) {
    asm volatile("cp.async.ca.shared.global [%0], [%1], 16;\n" :: "r"(saddr), "l"(gaddr));
}
__device__ __forceinline__ void cp_commit() {
    asm volatile("cp.async.commit_group;\n" ::: "memory");
}
template<int N>
__device__ __forceinline__ void cp_wait() {
    asm volatile("cp.async.wait_group %0;\n" :: "n"(N) : "memory");
}

__device__ __forceinline__ float gelu_tanh_f(float x) {
    float x3 = x * x * x;
    return 0.5f * x * (1.0f + tanhf(0.7978845608028654f * (x + 0.044715f * x3)));
}

// ---------------------------------------------------------------------------
// Generic tf32 MMA GEMM, 4-stage cp.async pipeline, 256 threads (8 warps),
// 128x64 block tile, 32x32 warp tile (4x2 warp grid), 2 CTAs per SM:
//   C[M,N] = act(alpha * A[M,K] @ B[N,K]^T + bias)
// Requirements: M%128==0, N%64==0, K%32==0, all lds %4==0.
// Batched via blockIdx.z with strides sA, sB, sC.
// fp32 consumed as tf32 by tensor-core truncation.
// ---------------------------------------------------------------------------
#define GBM 128
#define GBN 64
#define GBK 32
#define GLD 36                          // 32 + 4 pad floats (row stride 144B)
#define NSTG 4
#define STAGE_F ((GBM + GBN) * GLD)     // floats per stage = 6912
#define GEMM_THREADS 256

template<int ACT>
__global__ void __launch_bounds__(GEMM_THREADS, 2)
gemm_tf32(const float* __restrict__ A, const float* __restrict__ B,
          const float* __restrict__ bias, float* __restrict__ C,
          int K, int lda, int ldb, int ldc,
          long long sA, long long sB, long long sC, float alpha)
{
    extern __shared__ float smem[];
    const uint32_t sbase = (uint32_t)__cvta_generic_to_shared(smem);

    const int tid  = threadIdx.x;
    const int lane = tid & 31;
    const int warp = tid >> 5;
    const int wm = warp & 3;          // 4 warps in M -> 32 rows each
    const int wn = warp >> 2;         // 2 warps in N -> 32 cols each
    const int g  = lane >> 2;         // 0..7
    const int tq = lane & 3;          // 0..3

    const long long bz = blockIdx.z;
    const float* Ab = A + bz * sA + (long long)(blockIdx.y * GBM) * lda;
    const float* Bb = B + bz * sB + (long long)(blockIdx.x * GBN) * ldb;
    float*       Cb = C + bz * sC;

    // cp.async mapping: A = 1024 16B-chunks (4/thread), B = 512 (2/thread)
    const int crow = tid >> 3;         // 0..31
    const int ccol = (tid & 7) * 4;    // float offset within row

    const int ntiles = K / GBK;

    auto load_stage = [&](int stage, int kt) {
        const uint32_t sa = sbase + (uint32_t)(stage * STAGE_F) * 4u;
        const uint32_t sb = sa + (uint32_t)(GBM * GLD) * 4u;
        const int koff = kt * GBK + ccol;
#pragma unroll
        for (int i = 0; i < 4; i++) {
            int r = crow + 32 * i;
            cp_async16(sa + (uint32_t)(r * GLD + ccol) * 4u, Ab + (long long)r * lda + koff);
        }
#pragma unroll
        for (int i = 0; i < 2; i++) {
            int r = crow + 32 * i;
            cp_async16(sb + (uint32_t)(r * GLD + ccol) * 4u, Bb + (long long)r * ldb + koff);
        }
    };

    float acc[2][4][4];
#pragma unroll
    for (int a = 0; a < 2; a++)
#pragma unroll
        for (int b = 0; b < 4; b++)
#pragma unroll
            for (int r = 0; r < 4; r++) acc[a][b][r] = 0.0f;

    // prologue: fill NSTG-1 stages
#pragma unroll
    for (int s = 0; s < NSTG - 1; s++) {
        if (s < ntiles) load_stage(s, s);
        cp_commit();
    }

    const int arow0 = (wm * 32 + g) * GLD + tq;
    const int brow0 = (wn * 32 + g) * GLD + tq;

    for (int kt = 0; kt < ntiles; kt++) {
        cp_wait<NSTG - 2>();
        __syncthreads();

        if (kt + NSTG - 1 < ntiles) load_stage((kt + NSTG - 1) % NSTG, kt + NSTG - 1);
        cp_commit();

        const int stage = kt % NSTG;
        const uint32_t* asu = (const uint32_t*)(smem + stage * STAGE_F);
        const uint32_t* bsu = asu + GBM * GLD;

#pragma unroll
        for (int kk = 0; kk < GBK; kk += 8) {
            uint32_t af[2][4], bf[4][2];
#pragma unroll
            for (int mi = 0; mi < 2; mi++) {
                int r0 = arow0 + mi * 16 * GLD + kk;
                af[mi][0] = asu[r0];
                af[mi][1] = asu[r0 + 8 * GLD];
                af[mi][2] = asu[r0 + 4];
                af[mi][3] = asu[r0 + 8 * GLD + 4];
            }
#pragma unroll
            for (int ni = 0; ni < 4; ni++) {
                int c0 = brow0 + ni * 8 * GLD + kk;
                bf[ni][0] = bsu[c0];
                bf[ni][1] = bsu[c0 + 4];
            }
#pragma unroll
            for (int mi = 0; mi < 2; mi++)
#pragma unroll
                for (int ni = 0; ni < 4; ni++)
                    mma_tf32(acc[mi][ni], af[mi], bf[ni]);
        }
    }

    // epilogue
    const int mb = blockIdx.y * GBM + wm * 32;
    const int nb = blockIdx.x * GBN + wn * 32;
#pragma unroll
    for (int mi = 0; mi < 2; mi++) {
        int row = mb + mi * 16 + g;
#pragma unroll
        for (int ni = 0; ni < 4; ni++) {
            int col = nb + ni * 8 + 2 * tq;
            float v0 = alpha * acc[mi][ni][0];
            float v1 = alpha * acc[mi][ni][1];
            float v2 = alpha * acc[mi][ni][2];
            float v3 = alpha * acc[mi][ni][3];
            if (bias != nullptr) {
                float b0 = bias[col], b1 = bias[col + 1];
                v0 += b0; v1 += b1; v2 += b0; v3 += b1;
            }
            if (ACT == 1) {
                v0 = gelu_tanh_f(v0); v1 = gelu_tanh_f(v1);
                v2 = gelu_tanh_f(v2); v3 = gelu_tanh_f(v3);
            }
            *(float2*)(Cb + (long long)row * ldc + col)       = make_float2(v0, v1);
            *(float2*)(Cb + (long long)(row + 8) * ldc + col) = make_float2(v2, v3);
        }
    }
}

// ---------------------------------------------------------------------------
// LayerNorm + modulation:  out = shift + (1+scale) * LN(x)  per row of 3072
// ---------------------------------------------------------------------------
__global__ void ln_mod_kernel(const float* __restrict__ x, const float* __restrict__ mod,
                              float* __restrict__ out)
{
    const int t = blockIdx.x;
    const float* xr = x + (size_t)t * HIDDEN;
    float* orow = out + (size_t)t * HIDDEN;

    float s = 0.f, s2 = 0.f;
    for (int c = threadIdx.x; c < HIDDEN; c += 256) {
        float v = xr[c];
        s += v; s2 += v * v;
    }
    const int lane = threadIdx.x & 31, wid = threadIdx.x >> 5;
#pragma unroll
    for (int o = 16; o > 0; o >>= 1) {
        s  += __shfl_xor_sync(0xffffffffu, s, o);
        s2 += __shfl_xor_sync(0xffffffffu, s2, o);
    }
    __shared__ float sh[16];
    if (lane == 0) { sh[wid] = s; sh[8 + wid] = s2; }
    __syncthreads();
    float S = 0.f, S2 = 0.f;
#pragma unroll
    for (int w = 0; w < 8; w++) { S += sh[w]; S2 += sh[8 + w]; }
    float mean = S * (1.0f / HIDDEN);
    float var  = S2 * (1.0f / HIDDEN) - mean * mean;
    float inv  = rsqrtf(var + 1e-6f);

    for (int c = threadIdx.x; c < HIDDEN; c += 256) {
        orow[c] = mod[c] + (1.0f + mod[HIDDEN + c]) * ((xr[c] - mean) * inv);
    }
}

// ---------------------------------------------------------------------------
// Per-(token, head): RMS norm q/k, RoPE, scatter into q/k [h][l][d], vT [h][d][l]
// ---------------------------------------------------------------------------
__global__ void rmsrope_kernel(const float* __restrict__ qkv,
                               const float* __restrict__ q_scale,
                               const float* __restrict__ k_scale,
                               const float* __restrict__ pe,
                               float* __restrict__ qo, float* __restrict__ ko,
                               float* __restrict__ vT, int l_off)
{
    const int t = blockIdx.x, h = blockIdx.y, d = threadIdx.x;
    const int l = l_off + t;
    const float* base = qkv + (size_t)t * (3 * HIDDEN) + h * HEAD_DIM;
    float qv = base[d];
    float kv = base[HIDDEN + d];
    float vv = base[2 * HIDDEN + d];

    const int lane = d & 31, wid = d >> 5;
    float qs = qv * qv, ks = kv * kv;
#pragma unroll
    for (int o = 16; o > 0; o >>= 1) {
        qs += __shfl_xor_sync(0xffffffffu, qs, o);
        ks += __shfl_xor_sync(0xffffffffu, ks, o);
    }
    __shared__ float red[8];
    if (lane == 0) { red[wid] = qs; red[4 + wid] = ks; }
    __syncthreads();
    float qm = (red[0] + red[1] + red[2] + red[3]) * (1.0f / HEAD_DIM);
    float km = (red[4] + red[5] + red[6] + red[7]) * (1.0f / HEAD_DIM);

    float qn = qv * rsqrtf(qm + 1e-6f) * q_scale[d];
    float kn = kv * rsqrtf(km + 1e-6f) * k_scale[d];

    __shared__ float sq[HEAD_DIM], sk[HEAD_DIM];
    sq[d] = qn; sk[d] = kn;
    __syncthreads();

    const int i = d >> 1;
    const float* p4 = pe + ((size_t)l * (HEAD_DIM / 2) + i) * 4;
    float rq, rk;
    if ((d & 1) == 0) {
        rq = p4[0] * sq[d] + p4[1] * sq[d + 1];
        rk = p4[0] * sk[d] + p4[1] * sk[d + 1];
    } else {
        rq = p4[2] * sq[d - 1] + p4[3] * sq[d];
        rk = p4[2] * sk[d - 1] + p4[3] * sk[d];
    }
    size_t qidx = ((size_t)h * SEQ_L + l) * HEAD_DIM + d;
    qo[qidx] = rq;
    ko[qidx] = rk;
    vT[((size_t)h * HEAD_DIM + d) * SEQ_L + l] = vv;
}

// ---------------------------------------------------------------------------
// Row softmax over 2048 columns
// ---------------------------------------------------------------------------
__global__ void softmax_kernel(float* __restrict__ s)
{
    float* p = s + (size_t)blockIdx.x * SEQ_L;
    float vals[8];
    float m = -1e30f;
#pragma unroll
    for (int i = 0; i < 8; i++) {
        vals[i] = p[threadIdx.x + i * 256];
        m = fmaxf(m, vals[i]);
    }
    const int lane = threadIdx.x & 31, wid = threadIdx.x >> 5;
#pragma unroll
    for (int o = 16; o > 0; o >>= 1) m = fmaxf(m, __shfl_xor_sync(0xffffffffu, m, o));
    __shared__ float sh[8];
    if (lane == 0) sh[wid] = m;
    __syncthreads();
    float M = sh[0];
#pragma unroll
    for (int w = 1; w < 8; w++) M = fmaxf(M, sh[w]);
    __syncthreads();

    float sum = 0.f;
#pragma unroll
    for (int i = 0; i < 8; i++) {
        vals[i] = __expf(vals[i] - M);
        sum += vals[i];
    }
#pragma unroll
    for (int o = 16; o > 0; o >>= 1) sum += __shfl_xor_sync(0xffffffffu, sum, o);
    if (lane == 0) sh[wid] = sum;
    __syncthreads();
    float S = 0.f;
#pragma unroll
    for (int w = 0; w < 8; w++) S += sh[w];
    float inv = 1.0f / S;
#pragma unroll
    for (int i = 0; i < 8; i++) p[threadIdx.x + i * 256] = vals[i] * inv;
}

// ---------------------------------------------------------------------------
// Gated residual: out = base + gate[c] * delta   (optional final clip)
// ---------------------------------------------------------------------------
template<bool CLIP>
__global__ void residual_kernel(const float* __restrict__ base, const float* __restrict__ delta,
                                const float* __restrict__ gate, float* __restrict__ out, int n)
{
    for (int i = blockIdx.x * blockDim.x + threadIdx.x; i < n; i += gridDim.x * blockDim.x) {
        float v = base[i] + gate[i % HIDDEN] * delta[i];
        if (CLIP) v = fminf(fmaxf(v, -65504.0f), 65504.0f);
        out[i] = v;
    }
}

// ---------------------------------------------------------------------------
// Host launcher
// ---------------------------------------------------------------------------
#define GEMM_SMEM (NSTG * STAGE_F * sizeof(float))   // 110592 bytes

static void launch_gemm(const float* A, const float* B, const float* bias, float* C,
                        int M, int N, int K, int lda, int ldb, int ldc,
                        long long sA, long long sB, long long sC,
                        int batch, float alpha, int act)
{
    dim3 grid(N / GBN, M / GBM, batch), block(GEMM_THREADS);
    if (act == 0)
        gemm_tf32<0><<<grid, block, GEMM_SMEM>>>(A, B, bias, C, K, lda, ldb, ldc, sA, sB, sC, alpha);
    else
        gemm_tf32<1><<<grid, block, GEMM_SMEM>>>(A, B, bias, C, K, lda, ldb, ldc, sA, sB, sC, alpha);
}

extern "C" void kernel_launch(void* const* d_in, const int* in_sizes, int n_in,
                              void* d_out, int out_size)
{
    static bool attr_done = false;
    if (!attr_done) {
        cudaFuncSetAttribute(gemm_tf32<0>, cudaFuncAttributeMaxDynamicSharedMemorySize, GEMM_SMEM);
        cudaFuncSetAttribute(gemm_tf32<1>, cudaFuncAttributeMaxDynamicSharedMemorySize, GEMM_SMEM);
        attr_done = true;
    }

    const float* img         = (const float*)d_in[0];
    const float* txt         = (const float*)d_in[1];
    const float* img_mod1    = (const float*)d_in[2];
    const float* img_mod2    = (const float*)d_in[3];
    const float* txt_mod1    = (const float*)d_in[4];
    const float* txt_mod2    = (const float*)d_in[5];
    const float* img_qkv_w   = (const float*)d_in[6];
    const float* img_qkv_b   = (const float*)d_in[7];
    const float* img_q_scale = (const float*)d_in[8];
    const float* img_k_scale = (const float*)d_in[9];
    const float* img_proj_w  = (const float*)d_in[10];
    const float* img_proj_b  = (const float*)d_in[11];
    const float* img_mlp_w1  = (const float*)d_in[12];
    const float* img_mlp_b1  = (const float*)d_in[13];
    const float* img_mlp_w2  = (const float*)d_in[14];
    const float* img_mlp_b2  = (const float*)d_in[15];
    const float* txt_qkv_w   = (const float*)d_in[16];
    const float* txt_qkv_b   = (const float*)d_in[17];
    const float* txt_q_scale = (const float*)d_in[18];
    const float* txt_k_scale = (const float*)d_in[19];
    const float* txt_proj_w  = (const float*)d_in[20];
    const float* txt_proj_b  = (const float*)d_in[21];
    const float* txt_mlp_w1  = (const float*)d_in[22];
    const float* txt_mlp_b1  = (const float*)d_in[23];
    const float* txt_mlp_w2  = (const float*)d_in[24];
    const float* txt_mlp_b2  = (const float*)d_in[25];
    const float* pe          = (const float*)d_in[26];

    float *xm, *qkv_i, *qkv_t, *q, *k, *vT, *scores, *attn, *tmp, *hbuf;
    cudaGetSymbolAddress((void**)&xm, g_xm);
    cudaGetSymbolAddress((void**)&qkv_i, g_qkv_img);
    cudaGetSymbolAddress((void**)&qkv_t, g_qkv_txt);
    cudaGetSymbolAddress((void**)&q, g_q);
    cudaGetSymbolAddress((void**)&k, g_k);
    cudaGetSymbolAddress((void**)&vT, g_vT);
    cudaGetSymbolAddress((void**)&scores, g_scores);
    cudaGetSymbolAddress((void**)&attn, g_attn);
    cudaGetSymbolAddress((void**)&tmp, g_tmp);
    cudaGetSymbolAddress((void**)&hbuf, g_h);

    float* out_img = (float*)d_out;
    float* out_txt = out_img + (size_t)T_IMG * HIDDEN;

    const float attn_scale = 0.08838834764831845f;  // 1/sqrt(128)

    // ---- QKV for both streams ----
    ln_mod_kernel<<<T_IMG, 256>>>(img, img_mod1, xm);
    launch_gemm(xm, img_qkv_w, img_qkv_b, qkv_i, T_IMG, 3 * HIDDEN, HIDDEN,
                HIDDEN, HIDDEN, 3 * HIDDEN, 0, 0, 0, 1, 1.0f, 0);
    ln_mod_kernel<<<T_TXT, 256>>>(txt, txt_mod1, xm);
    launch_gemm(xm, txt_qkv_w, txt_qkv_b, qkv_t, T_TXT, 3 * HIDDEN, HIDDEN,
                HIDDEN, HIDDEN, 3 * HIDDEN, 0, 0, 0, 1, 1.0f, 0);

    // ---- RMS norm + RoPE + scatter (txt tokens first: l in [0,512), img [512,2048)) ----
    rmsrope_kernel<<<dim3(T_TXT, NUM_HEADS), HEAD_DIM>>>(qkv_t, txt_q_scale, txt_k_scale, pe, q, k, vT, 0);
    rmsrope_kernel<<<dim3(T_IMG, NUM_HEADS), HEAD_DIM>>>(qkv_i, img_q_scale, img_k_scale, pe, q, k, vT, T_TXT);

    // ---- Attention ----
    launch_gemm(q, k, nullptr, scores, SEQ_L, SEQ_L, HEAD_DIM,
                HEAD_DIM, HEAD_DIM, SEQ_L,
                (long long)SEQ_L * HEAD_DIM, (long long)SEQ_L * HEAD_DIM,
                (long long)SEQ_L * SEQ_L, NUM_HEADS, attn_scale, 0);
    softmax_kernel<<<NUM_HEADS * SEQ_L, 256>>>(scores);
    launch_gemm(scores, vT, nullptr, attn, SEQ_L, HEAD_DIM, SEQ_L,
                SEQ_L, SEQ_L, HIDDEN,
                (long long)SEQ_L * SEQ_L, (long long)HEAD_DIM * SEQ_L,
                (long long)HEAD_DIM, NUM_HEADS, 1.0f, 0);

    // ---- Attention projections + gated residuals ----
    launch_gemm(attn + (size_t)T_TXT * HIDDEN, img_proj_w, img_proj_b, tmp,
                T_IMG, HIDDEN, HIDDEN, HIDDEN, HIDDEN, HIDDEN, 0, 0, 0, 1, 1.0f, 0);
    residual_kernel<false><<<4096, 256>>>(img, tmp, img_mod1 + 2 * HIDDEN, out_img, T_IMG * HIDDEN);

    launch_gemm(attn, txt_proj_w, txt_proj_b, tmp,
                T_TXT, HIDDEN, HIDDEN, HIDDEN, HIDDEN, HIDDEN, 0, 0, 0, 1, 1.0f, 0);
    residual_kernel<false><<<2048, 256>>>(txt, tmp, txt_mod1 + 2 * HIDDEN, out_txt, T_TXT * HIDDEN);

    // ---- img MLP ----
    ln_mod_kernel<<<T_IMG, 256>>>(out_img, img_mod2, xm);
    launch_gemm(xm, img_mlp_w1, img_mlp_b1, hbuf, T_IMG, MLPD, HIDDEN,
                HIDDEN, HIDDEN, MLPD, 0, 0, 0, 1, 1.0f, 1);
    launch_gemm(hbuf, img_mlp_w2, img_mlp_b2, tmp, T_IMG, HIDDEN, MLPD,
                MLPD, MLPD, HIDDEN, 0, 0, 0, 1, 1.0f, 0);
    residual_kernel<false><<<4096, 256>>>(out_img, tmp, img_mod2 + 2 * HIDDEN, out_img, T_IMG * HIDDEN);

    // ---- txt MLP (final residual fused with clip) ----
    ln_mod_kernel<<<T_TXT, 256>>>(out_txt, txt_mod2, xm);
    launch_gemm(xm, txt_mlp_w1, txt_mlp_b1, hbuf, T_TXT, MLPD, HIDDEN,
                HIDDEN, HIDDEN, MLPD, 0, 0, 0, 1, 1.0f, 1);
    launch_gemm(hbuf, txt_mlp_w2, txt_mlp_b2, tmp, T_TXT, HIDDEN, MLPD,
                MLPD, MLPD, HIDDEN, 0, 0, 0, 1, 1.0f, 0);
    residual_kernel<true><<<2048, 256>>>(out_txt, tmp, txt_mod2 + 2 * HIDDEN, out_txt, T_TXT * HIDDEN);
}

// round 9
// speedup vs baseline: 2.1391x; 2.1391x over previous
#include <cuda_runtime.h>
#include <cuda_fp16.h>
#include <cstdint>
#include <cstdio>

// ---------------------------------------------------------------------------
// Problem constants
// ---------------------------------------------------------------------------
#define NUM_HEADS 24
#define HEAD_DIM  128
#define HIDDEN    3072
#define MLPD      12288
#define T_IMG     1536
#define T_TXT     512
#define SEQ_L     2048   // T_IMG + T_TXT

// ---------------------------------------------------------------------------
// Scratch (device globals; allocation-free per harness rules).
// All fp16 buffers 16B-aligned for cp.async / vector access.
// ---------------------------------------------------------------------------
__device__ __align__(16) __half g_xm16[(size_t)T_IMG * HIDDEN];
__device__ float  g_qkv_img[(size_t)T_IMG * 3 * HIDDEN];
__device__ float  g_qkv_txt[(size_t)T_TXT * 3 * HIDDEN];
__device__ __align__(16) __half g_q16[(size_t)NUM_HEADS * SEQ_L * HEAD_DIM];
__device__ __align__(16) __half g_k16[(size_t)NUM_HEADS * SEQ_L * HEAD_DIM];
__device__ __align__(16) __half g_vT16[(size_t)NUM_HEADS * HEAD_DIM * SEQ_L];
__device__ float  g_scores[(size_t)NUM_HEADS * SEQ_L * SEQ_L];    // 402 MB
__device__ __align__(16) __half g_probs16[(size_t)NUM_HEADS * SEQ_L * SEQ_L];   // 201 MB
__device__ __align__(16) __half g_attn16[(size_t)SEQ_L * HIDDEN];
__device__ float  g_tmp[(size_t)T_IMG * HIDDEN];
__device__ __align__(16) __half g_h16[(size_t)T_IMG * MLPD];

// fp16 weights (converted once per launch)
__device__ __align__(16) __half w16_img_qkv[(size_t)3 * HIDDEN * HIDDEN];
__device__ __align__(16) __half w16_txt_qkv[(size_t)3 * HIDDEN * HIDDEN];
__device__ __align__(16) __half w16_img_proj[(size_t)HIDDEN * HIDDEN];
__device__ __align__(16) __half w16_txt_proj[(size_t)HIDDEN * HIDDEN];
__device__ __align__(16) __half w16_img_mlp1[(size_t)MLPD * HIDDEN];
__device__ __align__(16) __half w16_img_mlp2[(size_t)HIDDEN * MLPD];
__device__ __align__(16) __half w16_txt_mlp1[(size_t)MLPD * HIDDEN];
__device__ __align__(16) __half w16_txt_mlp2[(size_t)HIDDEN * MLPD];

// ---------------------------------------------------------------------------
// Helpers
// ---------------------------------------------------------------------------
__device__ __forceinline__ void mma_fp16(float* d, const uint32_t* a, const uint32_t* b) {
    asm volatile(
        "mma.sync.aligned.m16n8k16.row.col.f32.f16.f16.f32 "
        "{%0,%1,%2,%3}, {%4,%5,%6,%7}, {%8,%9}, {%0,%1,%2,%3};\n"
        : "+f"(d[0]), "+f"(d[1]), "+f"(d[2]), "+f"(d[3])
        : "r"(a[0]), "r"(a[1]), "r"(a[2]), "r"(a[3]), "r"(b[0]), "r"(b[1]));
}

__device__ __forceinline__ void cp_async16(uint32_t saddr, const void* gaddr) {
    asm volatile("cp.async.ca.shared.global [%0], [%1], 16;\n" :: "r"(saddr), "l"(gaddr));
}
__device__ __forceinline__ void cp_commit() {
    asm volatile("cp.async.commit_group;\n" ::: "memory");
}
template<int N>
__device__ __forceinline__ void cp_wait() {
    asm volatile("cp.async.wait_group %0;\n" :: "n"(N) : "memory");
}

__device__ __forceinline__ float gelu_tanh_f(float x) {
    float x3 = x * x * x;
    return 0.5f * x * (1.0f + tanhf(0.7978845608028654f * (x + 0.044715f * x3)));
}

// ---------------------------------------------------------------------------
// fp16 MMA GEMM, 3-stage cp.async pipeline, 256 threads (8 warps),
// 128x128x64(fp16) block tile, 64x32 warp tile (2x4 warp grid):
//   C[M,N] = act(alpha * A[M,K] @ B[N,K]^T + bias)
// A, B are fp16 in gmem. Outputs: fp32 C (if OUT32), fp16 C16 (if OUT16).
// M%128==0, N%128==0, K%64==0, lda/ldb %8==0 (16B cp.async chunks).
// Batched via blockIdx.z with element strides sA, sB, sC.
// Row stride GLD=36 u32 = 144 B: 16B-aligned for cp.async, and fragment
// LDS banks = (4*g + tq) -> conflict-free (same pattern as verified fp32).
// ---------------------------------------------------------------------------
#define GBM 128
#define GBN 128
#define GBK 64                          // fp16 K elements per tile (128B rows)
#define GLD 36                          // u32 stride per row (32 data + 4 pad)
#define NSTG 3
#define STAGE_U32 (2 * GBM * GLD)       // A + B tiles = 9216 u32 = 36864 B
#define GEMM_SMEM (NSTG * STAGE_U32 * 4)  // 110592 bytes

template<int ACT, int OUT32, int OUT16>
__global__ void __launch_bounds__(256, 1)
gemm_fp16(const __half* __restrict__ A, const __half* __restrict__ B,
          const float* __restrict__ bias, float* __restrict__ C,
          __half* __restrict__ C16,
          int K, int lda, int ldb, int ldc,
          long long sA, long long sB, long long sC, float alpha)
{
    extern __shared__ uint32_t smem[];
    const uint32_t sbase = (uint32_t)__cvta_generic_to_shared(smem);

    const int tid  = threadIdx.x;
    const int lane = tid & 31;
    const int warp = tid >> 5;
    const int wm = warp & 1;          // 2 warps in M -> 64 rows each
    const int wn = warp >> 1;         // 4 warps in N -> 32 cols each
    const int g  = lane >> 2;         // 0..7
    const int tq = lane & 3;          // 0..3

    const long long bz = blockIdx.z;
    const __half* Ab = A + bz * sA + (long long)(blockIdx.y * GBM) * lda;
    const __half* Bb = B + bz * sB + (long long)(blockIdx.x * GBN) * ldb;

    // cp.async: per matrix per stage 128 rows x 8 chunks(16B) = 1024; 4/thread
    const int crow = tid >> 3;          // 0..31
    const int cch  = tid & 7;           // chunk col 0..7
    const int ccolh = cch * 8;          // fp16 col
    const int ccolu = cch * 4;          // u32 col

    const int ntiles = K / GBK;

    auto load_stage = [&](int stage, int kt) {
        const uint32_t sa = sbase + (uint32_t)(stage * STAGE_U32) * 4u;
        const uint32_t sb = sa + (uint32_t)(GBM * GLD) * 4u;
        const int koff = kt * GBK + ccolh;
#pragma unroll
        for (int i = 0; i < 4; i++) {
            int r = crow + 32 * i;
            cp_async16(sa + (uint32_t)(r * GLD + ccolu) * 4u, Ab + (long long)r * lda + koff);
            cp_async16(sb + (uint32_t)(r * GLD + ccolu) * 4u, Bb + (long long)r * ldb + koff);
        }
    };

    float acc[4][4][4];
#pragma unroll
    for (int a = 0; a < 4; a++)
#pragma unroll
        for (int b = 0; b < 4; b++)
#pragma unroll
            for (int r = 0; r < 4; r++) acc[a][b][r] = 0.0f;

#pragma unroll
    for (int s = 0; s < NSTG - 1; s++) {
        if (s < ntiles) load_stage(s, s);
        cp_commit();
    }

    const int arow0 = (wm * 64 + g) * GLD + tq;
    const int brow0 = (wn * 32 + g) * GLD + tq;

    for (int kt = 0; kt < ntiles; kt++) {
        cp_wait<NSTG - 2>();
        __syncthreads();

        if (kt + NSTG - 1 < ntiles) load_stage((kt + NSTG - 1) % NSTG, kt + NSTG - 1);
        cp_commit();

        const uint32_t* asu = smem + (kt % NSTG) * STAGE_U32;
        const uint32_t* bsu = asu + GBM * GLD;

#pragma unroll
        for (int ks = 0; ks < GBK / 16; ks++) {     // 4 k16 steps
            const int kk = ks * 8;                  // u32 col offset
            uint32_t af[4][4], bf[4][2];
#pragma unroll
            for (int mi = 0; mi < 4; mi++) {
                int r0 = arow0 + mi * 16 * GLD + kk;
                af[mi][0] = asu[r0];
                af[mi][1] = asu[r0 + 8 * GLD];
                af[mi][2] = asu[r0 + 4];
                af[mi][3] = asu[r0 + 8 * GLD + 4];
            }
#pragma unroll
            for (int ni = 0; ni < 4; ni++) {
                int c0 = brow0 + ni * 8 * GLD + kk;
                bf[ni][0] = bsu[c0];
                bf[ni][1] = bsu[c0 + 4];
            }
#pragma unroll
            for (int mi = 0; mi < 4; mi++)
#pragma unroll
                for (int ni = 0; ni < 4; ni++)
                    mma_fp16(acc[mi][ni], af[mi], bf[ni]);
        }
    }

    // epilogue
    const int mb = blockIdx.y * GBM + wm * 64;
    const int nb = blockIdx.x * GBN + wn * 32;
    float*  C32b = (OUT32) ? (C + bz * sC)   : nullptr;
    __half* C16b = (OUT16) ? (C16 + bz * sC) : nullptr;

#pragma unroll
    for (int mi = 0; mi < 4; mi++) {
        int row = mb + mi * 16 + g;
#pragma unroll
        for (int ni = 0; ni < 4; ni++) {
            int col = nb + ni * 8 + 2 * tq;
            float v0 = alpha * acc[mi][ni][0];
            float v1 = alpha * acc[mi][ni][1];
            float v2 = alpha * acc[mi][ni][2];
            float v3 = alpha * acc[mi][ni][3];
            if (bias != nullptr) {
                float b0 = bias[col], b1 = bias[col + 1];
                v0 += b0; v1 += b1; v2 += b0; v3 += b1;
            }
            if (ACT == 1) {
                v0 = gelu_tanh_f(v0); v1 = gelu_tanh_f(v1);
                v2 = gelu_tanh_f(v2); v3 = gelu_tanh_f(v3);
            }
            if (OUT32) {
                *(float2*)(C32b + (long long)row * ldc + col)       = make_float2(v0, v1);
                *(float2*)(C32b + (long long)(row + 8) * ldc + col) = make_float2(v2, v3);
            }
            if (OUT16) {
                *(__half2*)(C16b + (long long)row * ldc + col)       = __floats2half2_rn(v0, v1);
                *(__half2*)(C16b + (long long)(row + 8) * ldc + col) = __floats2half2_rn(v2, v3);
            }
        }
    }
}

// ---------------------------------------------------------------------------
// fp32 -> fp16 conversion (weights), n % 4 == 0
// ---------------------------------------------------------------------------
__global__ void f32_to_f16_kernel(const float* __restrict__ src, __half* __restrict__ dst,
                                  long long n)
{
    long long i = ((long long)blockIdx.x * blockDim.x + threadIdx.x) * 4;
    long long stride = (long long)gridDim.x * blockDim.x * 4;
    for (; i < n; i += stride) {
        float4 v = *(const float4*)(src + i);
        __half2 h0 = __floats2half2_rn(v.x, v.y);
        __half2 h1 = __floats2half2_rn(v.z, v.w);
        *(__half2*)(dst + i)     = h0;
        *(__half2*)(dst + i + 2) = h1;
    }
}

// ---------------------------------------------------------------------------
// LayerNorm + modulation -> fp16:  out = shift + (1+scale) * LN(x)
// ---------------------------------------------------------------------------
__global__ void ln_mod_kernel(const float* __restrict__ x, const float* __restrict__ mod,
                              __half* __restrict__ out)
{
    const int t = blockIdx.x;
    const float* xr = x + (size_t)t * HIDDEN;
    __half* orow = out + (size_t)t * HIDDEN;

    float s = 0.f, s2 = 0.f;
    for (int c = threadIdx.x; c < HIDDEN; c += 256) {
        float v = xr[c];
        s += v; s2 += v * v;
    }
    const int lane = threadIdx.x & 31, wid = threadIdx.x >> 5;
#pragma unroll
    for (int o = 16; o > 0; o >>= 1) {
        s  += __shfl_xor_sync(0xffffffffu, s, o);
        s2 += __shfl_xor_sync(0xffffffffu, s2, o);
    }
    __shared__ float sh[16];
    if (lane == 0) { sh[wid] = s; sh[8 + wid] = s2; }
    __syncthreads();
    float S = 0.f, S2 = 0.f;
#pragma unroll
    for (int w = 0; w < 8; w++) { S += sh[w]; S2 += sh[8 + w]; }
    float mean = S * (1.0f / HIDDEN);
    float var  = S2 * (1.0f / HIDDEN) - mean * mean;
    float inv  = rsqrtf(var + 1e-6f);

    for (int c = threadIdx.x; c < HIDDEN; c += 256) {
        float v = mod[c] + (1.0f + mod[HIDDEN + c]) * ((xr[c] - mean) * inv);
        orow[c] = __float2half_rn(v);
    }
}

// ---------------------------------------------------------------------------
// Per-(token, head): RMS norm q/k, RoPE, scatter fp16 q/k [h][l][d], vT [h][d][l]
// ---------------------------------------------------------------------------
__global__ void rmsrope_kernel(const float* __restrict__ qkv,
                               const float* __restrict__ q_scale,
                               const float* __restrict__ k_scale,
                               const float* __restrict__ pe,
                               __half* __restrict__ qo, __half* __restrict__ ko,
                               __half* __restrict__ vT, int l_off)
{
    const int t = blockIdx.x, h = blockIdx.y, d = threadIdx.x;
    const int l = l_off + t;
    const float* base = qkv + (size_t)t * (3 * HIDDEN) + h * HEAD_DIM;
    float qv = base[d];
    float kv = base[HIDDEN + d];
    float vv = base[2 * HIDDEN + d];

    const int lane = d & 31, wid = d >> 5;
    float qs = qv * qv, ks = kv * kv;
#pragma unroll
    for (int o = 16; o > 0; o >>= 1) {
        qs += __shfl_xor_sync(0xffffffffu, qs, o);
        ks += __shfl_xor_sync(0xffffffffu, ks, o);
    }
    __shared__ float red[8];
    if (lane == 0) { red[wid] = qs; red[4 + wid] = ks; }
    __syncthreads();
    float qm = (red[0] + red[1] + red[2] + red[3]) * (1.0f / HEAD_DIM);
    float km = (red[4] + red[5] + red[6] + red[7]) * (1.0f / HEAD_DIM);

    float qn = qv * rsqrtf(qm + 1e-6f) * q_scale[d];
    float kn = kv * rsqrtf(km + 1e-6f) * k_scale[d];

    __shared__ float sq[HEAD_DIM], sk[HEAD_DIM];
    sq[d] = qn; sk[d] = kn;
    __syncthreads();

    const int i = d >> 1;
    const float* p4 = pe + ((size_t)l * (HEAD_DIM / 2) + i) * 4;
    float rq, rk;
    if ((d & 1) == 0) {
        rq = p4[0] * sq[d] + p4[1] * sq[d + 1];
        rk = p4[0] * sk[d] + p4[1] * sk[d + 1];
    } else {
        rq = p4[2] * sq[d - 1] + p4[3] * sq[d];
        rk = p4[2] * sk[d - 1] + p4[3] * sk[d];
    }
    size_t qidx = ((size_t)h * SEQ_L + l) * HEAD_DIM + d;
    qo[qidx] = __float2half_rn(rq);
    ko[qidx] = __float2half_rn(rk);
    vT[((size_t)h * HEAD_DIM + d) * SEQ_L + l] = __float2half_rn(vv);
}

// ---------------------------------------------------------------------------
// Row softmax over 2048 columns: fp32 scores in, fp16 probs out
// ---------------------------------------------------------------------------
__global__ void softmax_kernel(const float* __restrict__ s, __half* __restrict__ p16)
{
    const float* p = s + (size_t)blockIdx.x * SEQ_L;
    __half* o = p16 + (size_t)blockIdx.x * SEQ_L;
    float vals[8];
    float m = -1e30f;
#pragma unroll
    for (int i = 0; i < 8; i++) {
        vals[i] = p[threadIdx.x + i * 256];
        m = fmaxf(m, vals[i]);
    }
    const int lane = threadIdx.x & 31, wid = threadIdx.x >> 5;
#pragma unroll
    for (int o2 = 16; o2 > 0; o2 >>= 1) m = fmaxf(m, __shfl_xor_sync(0xffffffffu, m, o2));
    __shared__ float sh[8];
    if (lane == 0) sh[wid] = m;
    __syncthreads();
    float M = sh[0];
#pragma unroll
    for (int w = 1; w < 8; w++) M = fmaxf(M, sh[w]);
    __syncthreads();

    float sum = 0.f;
#pragma unroll
    for (int i = 0; i < 8; i++) {
        vals[i] = __expf(vals[i] - M);
        sum += vals[i];
    }
#pragma unroll
    for (int o2 = 16; o2 > 0; o2 >>= 1) sum += __shfl_xor_sync(0xffffffffu, sum, o2);
    if (lane == 0) sh[wid] = sum;
    __syncthreads();
    float S = 0.f;
#pragma unroll
    for (int w = 0; w < 8; w++) S += sh[w];
    float inv = 1.0f / S;
#pragma unroll
    for (int i = 0; i < 8; i++) o[threadIdx.x + i * 256] = __float2half_rn(vals[i] * inv);
}

// ---------------------------------------------------------------------------
// Gated residual: out = base + gate[c] * delta   (optional final clip)
// ---------------------------------------------------------------------------
template<bool CLIP>
__global__ void residual_kernel(const float* __restrict__ base, const float* __restrict__ delta,
                                const float* __restrict__ gate, float* __restrict__ out, int n)
{
    for (int i = blockIdx.x * blockDim.x + threadIdx.x; i < n; i += gridDim.x * blockDim.x) {
        float v = base[i] + gate[i % HIDDEN] * delta[i];
        if (CLIP) v = fminf(fmaxf(v, -65504.0f), 65504.0f);
        out[i] = v;
    }
}

// ---------------------------------------------------------------------------
// Host launcher
// ---------------------------------------------------------------------------
static void launch_gemm(const __half* A, const __half* B, const float* bias,
                        float* C, __half* C16,
                        int M, int N, int K, int lda, int ldb, int ldc,
                        long long sA, long long sB, long long sC,
                        int batch, float alpha, int act, int out32, int out16)
{
    dim3 grid(N / GBN, M / GBM, batch), block(256);
    if (act == 0 && out32 && !out16)
        gemm_fp16<0,1,0><<<grid, block, GEMM_SMEM>>>(A, B, bias, C, C16, K, lda, ldb, ldc, sA, sB, sC, alpha);
    else if (act == 1 && !out32 && out16)
        gemm_fp16<1,0,1><<<grid, block, GEMM_SMEM>>>(A, B, bias, C, C16, K, lda, ldb, ldc, sA, sB, sC, alpha);
    else
        gemm_fp16<0,0,1><<<grid, block, GEMM_SMEM>>>(A, B, bias, C, C16, K, lda, ldb, ldc, sA, sB, sC, alpha);
}

static void conv_w(const float* src, __half* dst, long long n)
{
    f32_to_f16_kernel<<<1024, 256>>>(src, dst, n);
}

extern "C" void kernel_launch(void* const* d_in, const int* in_sizes, int n_in,
                              void* d_out, int out_size)
{
    static bool attr_done = false;
    if (!attr_done) {
        cudaFuncSetAttribute(gemm_fp16<0,1,0>, cudaFuncAttributeMaxDynamicSharedMemorySize, GEMM_SMEM);
        cudaFuncSetAttribute(gemm_fp16<1,0,1>, cudaFuncAttributeMaxDynamicSharedMemorySize, GEMM_SMEM);
        cudaFuncSetAttribute(gemm_fp16<0,0,1>, cudaFuncAttributeMaxDynamicSharedMemorySize, GEMM_SMEM);
        attr_done = true;
    }

    const float* img         = (const float*)d_in[0];
    const float* txt         = (const float*)d_in[1];
    const float* img_mod1    = (const float*)d_in[2];
    const float* img_mod2    = (const float*)d_in[3];
    const float* txt_mod1    = (const float*)d_in[4];
    const float* txt_mod2    = (const float*)d_in[5];
    const float* img_qkv_w   = (const float*)d_in[6];
    const float* img_qkv_b   = (const float*)d_in[7];
    const float* img_q_scale = (const float*)d_in[8];
    const float* img_k_scale = (const float*)d_in[9];
    const float* img_proj_w  = (const float*)d_in[10];
    const float* img_proj_b  = (const float*)d_in[11];
    const float* img_mlp_w1  = (const float*)d_in[12];
    const float* img_mlp_b1  = (const float*)d_in[13];
    const float* img_mlp_w2  = (const float*)d_in[14];
    const float* img_mlp_b2  = (const float*)d_in[15];
    const float* txt_qkv_w   = (const float*)d_in[16];
    const float* txt_qkv_b   = (const float*)d_in[17];
    const float* txt_q_scale = (const float*)d_in[18];
    const float* txt_k_scale = (const float*)d_in[19];
    const float* txt_proj_w  = (const float*)d_in[20];
    const float* txt_proj_b  = (const float*)d_in[21];
    const float* txt_mlp_w1  = (const float*)d_in[22];
    const float* txt_mlp_b1  = (const float*)d_in[23];
    const float* txt_mlp_w2  = (const float*)d_in[24];
    const float* txt_mlp_b2  = (const float*)d_in[25];
    const float* pe          = (const float*)d_in[26];

    __half *xm16, *q16, *k16, *vT16, *probs16, *attn16, *h16;
    __half *wiq, *wtq, *wip, *wtp, *wim1, *wim2, *wtm1, *wtm2;
    float *qkv_i, *qkv_t, *scores, *tmp;
    cudaGetSymbolAddress((void**)&xm16, g_xm16);
    cudaGetSymbolAddress((void**)&qkv_i, g_qkv_img);
    cudaGetSymbolAddress((void**)&qkv_t, g_qkv_txt);
    cudaGetSymbolAddress((void**)&q16, g_q16);
    cudaGetSymbolAddress((void**)&k16, g_k16);
    cudaGetSymbolAddress((void**)&vT16, g_vT16);
    cudaGetSymbolAddress((void**)&scores, g_scores);
    cudaGetSymbolAddress((void**)&probs16, g_probs16);
    cudaGetSymbolAddress((void**)&attn16, g_attn16);
    cudaGetSymbolAddress((void**)&tmp, g_tmp);
    cudaGetSymbolAddress((void**)&h16, g_h16);
    cudaGetSymbolAddress((void**)&wiq, w16_img_qkv);
    cudaGetSymbolAddress((void**)&wtq, w16_txt_qkv);
    cudaGetSymbolAddress((void**)&wip, w16_img_proj);
    cudaGetSymbolAddress((void**)&wtp, w16_txt_proj);
    cudaGetSymbolAddress((void**)&wim1, w16_img_mlp1);
    cudaGetSymbolAddress((void**)&wim2, w16_img_mlp2);
    cudaGetSymbolAddress((void**)&wtm1, w16_txt_mlp1);
    cudaGetSymbolAddress((void**)&wtm2, w16_txt_mlp2);

    float* out_img = (float*)d_out;
    float* out_txt = out_img + (size_t)T_IMG * HIDDEN;

    const float attn_scale = 0.08838834764831845f;  // 1/sqrt(128)

    // ---- weight conversions (fp32 -> fp16) ----
    conv_w(img_qkv_w, wiq, (long long)3 * HIDDEN * HIDDEN);
    conv_w(txt_qkv_w, wtq, (long long)3 * HIDDEN * HIDDEN);
    conv_w(img_proj_w, wip, (long long)HIDDEN * HIDDEN);
    conv_w(txt_proj_w, wtp, (long long)HIDDEN * HIDDEN);
    conv_w(img_mlp_w1, wim1, (long long)MLPD * HIDDEN);
    conv_w(img_mlp_w2, wim2, (long long)HIDDEN * MLPD);
    conv_w(txt_mlp_w1, wtm1, (long long)MLPD * HIDDEN);
    conv_w(txt_mlp_w2, wtm2, (long long)HIDDEN * MLPD);

    // ---- QKV for both streams ----
    ln_mod_kernel<<<T_IMG, 256>>>(img, img_mod1, xm16);
    launch_gemm(xm16, wiq, img_qkv_b, qkv_i, nullptr, T_IMG, 3 * HIDDEN, HIDDEN,
                HIDDEN, HIDDEN, 3 * HIDDEN, 0, 0, 0, 1, 1.0f, 0, 1, 0);
    ln_mod_kernel<<<T_TXT, 256>>>(txt, txt_mod1, xm16);
    launch_gemm(xm16, wtq, txt_qkv_b, qkv_t, nullptr, T_TXT, 3 * HIDDEN, HIDDEN,
                HIDDEN, HIDDEN, 3 * HIDDEN, 0, 0, 0, 1, 1.0f, 0, 1, 0);

    // ---- RMS norm + RoPE + scatter (txt tokens: l in [0,512), img [512,2048)) ----
    rmsrope_kernel<<<dim3(T_TXT, NUM_HEADS), HEAD_DIM>>>(qkv_t, txt_q_scale, txt_k_scale, pe, q16, k16, vT16, 0);
    rmsrope_kernel<<<dim3(T_IMG, NUM_HEADS), HEAD_DIM>>>(qkv_i, img_q_scale, img_k_scale, pe, q16, k16, vT16, T_TXT);

    // ---- Attention ----
    launch_gemm(q16, k16, nullptr, scores, nullptr, SEQ_L, SEQ_L, HEAD_DIM,
                HEAD_DIM, HEAD_DIM, SEQ_L,
                (long long)SEQ_L * HEAD_DIM, (long long)SEQ_L * HEAD_DIM,
                (long long)SEQ_L * SEQ_L, NUM_HEADS, attn_scale, 0, 1, 0);
    softmax_kernel<<<NUM_HEADS * SEQ_L, 256>>>(scores, probs16);
    launch_gemm(probs16, vT16, nullptr, nullptr, attn16, SEQ_L, HEAD_DIM, SEQ_L,
                SEQ_L, SEQ_L, HIDDEN,
                (long long)SEQ_L * SEQ_L, (long long)HEAD_DIM * SEQ_L,
                (long long)HEAD_DIM, NUM_HEADS, 1.0f, 0, 0, 1);

    // ---- Attention projections + gated residuals ----
    launch_gemm(attn16 + (size_t)T_TXT * HIDDEN, wip, img_proj_b, tmp, nullptr,
                T_IMG, HIDDEN, HIDDEN, HIDDEN, HIDDEN, HIDDEN, 0, 0, 0, 1, 1.0f, 0, 1, 0);
    residual_kernel<false><<<4096, 256>>>(img, tmp, img_mod1 + 2 * HIDDEN, out_img, T_IMG * HIDDEN);

    launch_gemm(attn16, wtp, txt_proj_b, tmp, nullptr,
                T_TXT, HIDDEN, HIDDEN, HIDDEN, HIDDEN, HIDDEN, 0, 0, 0, 1, 1.0f, 0, 1, 0);
    residual_kernel<false><<<2048, 256>>>(txt, tmp, txt_mod1 + 2 * HIDDEN, out_txt, T_TXT * HIDDEN);

    // ---- img MLP ----
    ln_mod_kernel<<<T_IMG, 256>>>(out_img, img_mod2, xm16);
    launch_gemm(xm16, wim1, img_mlp_b1, nullptr, h16, T_IMG, MLPD, HIDDEN,
                HIDDEN, HIDDEN, MLPD, 0, 0, 0, 1, 1.0f, 1, 0, 1);
    launch_gemm(h16, wim2, img_mlp_b2, tmp, nullptr, T_IMG, HIDDEN, MLPD,
                MLPD, MLPD, HIDDEN, 0, 0, 0, 1, 1.0f, 0, 1, 0);
    residual_kernel<false><<<4096, 256>>>(out_img, tmp, img_mod2 + 2 * HIDDEN, out_img, T_IMG * HIDDEN);

    // ---- txt MLP (final residual fused with clip) ----
    ln_mod_kernel<<<T_TXT, 256>>>(out_txt, txt_mod2, xm16);
    launch_gemm(xm16, wtm1, txt_mlp_b1, nullptr, h16, T_TXT, MLPD, HIDDEN,
                HIDDEN, HIDDEN, MLPD, 0, 0, 0, 1, 1.0f, 1, 0, 1);
    launch_gemm(h16, wtm2, txt_mlp_b2, tmp, nullptr, T_TXT, HIDDEN, MLPD,
                MLPD, MLPD, HIDDEN, 0, 0, 0, 1, 1.0f, 0, 1, 0);
    residual_kernel<true><<<2048, 256>>>(out_txt, tmp, txt_mod2 + 2 * HIDDEN, out_txt, T_TXT * HIDDEN);
}

// round 13
// speedup vs baseline: 2.1395x; 1.0002x over previous
#include <cuda_runtime.h>
#include <cuda_fp16.h>
#include <cstdint>
#include <cstdio>

// ---------------------------------------------------------------------------
// Problem constants
// ---------------------------------------------------------------------------
#define NUM_HEADS 24
#define HEAD_DIM  128
#define HIDDEN    3072
#define MLPD      12288
#define T_IMG     1536
#define T_TXT     512
#define SEQ_L     2048   // T_IMG + T_TXT

// ---------------------------------------------------------------------------
// Scratch (device globals; allocation-free per harness rules).
// All fp16 buffers 16B-aligned for cp.async / vector access.
// ---------------------------------------------------------------------------
__device__ __align__(16) __half g_xm16[(size_t)T_IMG * HIDDEN];
__device__ float  g_qkv_img[(size_t)T_IMG * 3 * HIDDEN];
__device__ float  g_qkv_txt[(size_t)T_TXT * 3 * HIDDEN];
__device__ __align__(16) __half g_q16[(size_t)NUM_HEADS * SEQ_L * HEAD_DIM];
__device__ __align__(16) __half g_k16[(size_t)NUM_HEADS * SEQ_L * HEAD_DIM];
__device__ __align__(16) __half g_vT16[(size_t)NUM_HEADS * HEAD_DIM * SEQ_L];
__device__ float  g_scores[(size_t)NUM_HEADS * SEQ_L * SEQ_L];    // 402 MB
__device__ __align__(16) __half g_probs16[(size_t)NUM_HEADS * SEQ_L * SEQ_L];   // 201 MB
__device__ __align__(16) __half g_attn16[(size_t)SEQ_L * HIDDEN];
__device__ float  g_tmp[(size_t)T_IMG * HIDDEN];
__device__ __align__(16) __half g_h16[(size_t)T_IMG * MLPD];

// fp16 weights (converted once per launch)
__device__ __align__(16) __half w16_img_qkv[(size_t)3 * HIDDEN * HIDDEN];
__device__ __align__(16) __half w16_txt_qkv[(size_t)3 * HIDDEN * HIDDEN];
__device__ __align__(16) __half w16_img_proj[(size_t)HIDDEN * HIDDEN];
__device__ __align__(16) __half w16_txt_proj[(size_t)HIDDEN * HIDDEN];
__device__ __align__(16) __half w16_img_mlp1[(size_t)MLPD * HIDDEN];
__device__ __align__(16) __half w16_img_mlp2[(size_t)HIDDEN * MLPD];
__device__ __align__(16) __half w16_txt_mlp1[(size_t)MLPD * HIDDEN];
__device__ __align__(16) __half w16_txt_mlp2[(size_t)HIDDEN * MLPD];

// ---------------------------------------------------------------------------
// Helpers
// ---------------------------------------------------------------------------
__device__ __forceinline__ void mma_fp16(float* d, const uint32_t* a, const uint32_t* b) {
    asm volatile(
        "mma.sync.aligned.m16n8k16.row.col.f32.f16.f16.f32 "
        "{%0,%1,%2,%3}, {%4,%5,%6,%7}, {%8,%9}, {%0,%1,%2,%3};\n"
        : "+f"(d[0]), "+f"(d[1]), "+f"(d[2]), "+f"(d[3])
        : "r"(a[0]), "r"(a[1]), "r"(a[2]), "r"(a[3]), "r"(b[0]), "r"(b[1]));
}

__device__ __forceinline__ void cp_async16(uint32_t saddr, const void* gaddr) {
    asm volatile("cp.async.ca.shared.global [%0], [%1], 16;\n" :: "r"(saddr), "l"(gaddr));
}
__device__ __forceinline__ void cp_commit() {
    asm volatile("cp.async.commit_group;\n" ::: "memory");
}
template<int N>
__device__ __forceinline__ void cp_wait() {
    asm volatile("cp.async.wait_group %0;\n" :: "n"(N) : "memory");
}

__device__ __forceinline__ float gelu_tanh_f(float x) {
    float x3 = x * x * x;
    return 0.5f * x * (1.0f + tanhf(0.7978845608028654f * (x + 0.044715f * x3)));
}

// ---------------------------------------------------------------------------
// fp16 MMA GEMM, 3-stage cp.async pipeline, 256 threads (8 warps),
// 128x128x64(fp16) block tile, 64x32 warp tile (2x4 warp grid):
//   C[M,N] = act(alpha * A[M,K] @ B[N,K]^T + bias)
// A, B are fp16 in gmem. Outputs: fp32 C (if OUT32), fp16 C16 (if OUT16).
// M%128==0, N%128==0, K%64==0, lda/ldb %8==0 (16B cp.async chunks).
// Batched via blockIdx.z with element strides sA, sB, sC.
// Row stride GLD=36 u32 = 144 B: 16B-aligned for cp.async, and fragment
// LDS banks = (4*g + tq) -> conflict-free (same pattern as verified fp32).
// ---------------------------------------------------------------------------
#define GBM 128
#define GBN 128
#define GBK 64                          // fp16 K elements per tile (128B rows)
#define GLD 36                          // u32 stride per row (32 data + 4 pad)
#define NSTG 3
#define STAGE_U32 (2 * GBM * GLD)       // A + B tiles = 9216 u32 = 36864 B
#define GEMM_SMEM (NSTG * STAGE_U32 * 4)  // 110592 bytes

template<int ACT, int OUT32, int OUT16>
__global__ void __launch_bounds__(256, 1)
gemm_fp16(const __half* __restrict__ A, const __half* __restrict__ B,
          const float* __restrict__ bias, float* __restrict__ C,
          __half* __restrict__ C16,
          int K, int lda, int ldb, int ldc,
          long long sA, long long sB, long long sC, float alpha)
{
    extern __shared__ uint32_t smem[];
    const uint32_t sbase = (uint32_t)__cvta_generic_to_shared(smem);

    const int tid  = threadIdx.x;
    const int lane = tid & 31;
    const int warp = tid >> 5;
    const int wm = warp & 1;          // 2 warps in M -> 64 rows each
    const int wn = warp >> 1;         // 4 warps in N -> 32 cols each
    const int g  = lane >> 2;         // 0..7
    const int tq = lane & 3;          // 0..3

    const long long bz = blockIdx.z;
    const __half* Ab = A + bz * sA + (long long)(blockIdx.y * GBM) * lda;
    const __half* Bb = B + bz * sB + (long long)(blockIdx.x * GBN) * ldb;

    // cp.async: per matrix per stage 128 rows x 8 chunks(16B) = 1024; 4/thread
    const int crow = tid >> 3;          // 0..31
    const int cch  = tid & 7;           // chunk col 0..7
    const int ccolh = cch * 8;          // fp16 col
    const int ccolu = cch * 4;          // u32 col

    const int ntiles = K / GBK;

    auto load_stage = [&](int stage, int kt) {
        const uint32_t sa = sbase + (uint32_t)(stage * STAGE_U32) * 4u;
        const uint32_t sb = sa + (uint32_t)(GBM * GLD) * 4u;
        const int koff = kt * GBK + ccolh;
#pragma unroll
        for (int i = 0; i < 4; i++) {
            int r = crow + 32 * i;
            cp_async16(sa + (uint32_t)(r * GLD + ccolu) * 4u, Ab + (long long)r * lda + koff);
            cp_async16(sb + (uint32_t)(r * GLD + ccolu) * 4u, Bb + (long long)r * ldb + koff);
        }
    };

    float acc[4][4][4];
#pragma unroll
    for (int a = 0; a < 4; a++)
#pragma unroll
        for (int b = 0; b < 4; b++)
#pragma unroll
            for (int r = 0; r < 4; r++) acc[a][b][r] = 0.0f;

#pragma unroll
    for (int s = 0; s < NSTG - 1; s++) {
        if (s < ntiles) load_stage(s, s);
        cp_commit();
    }

    const int arow0 = (wm * 64 + g) * GLD + tq;
    const int brow0 = (wn * 32 + g) * GLD + tq;

    for (int kt = 0; kt < ntiles; kt++) {
        cp_wait<NSTG - 2>();
        __syncthreads();

        if (kt + NSTG - 1 < ntiles) load_stage((kt + NSTG - 1) % NSTG, kt + NSTG - 1);
        cp_commit();

        const uint32_t* asu = smem + (kt % NSTG) * STAGE_U32;
        const uint32_t* bsu = asu + GBM * GLD;

#pragma unroll
        for (int ks = 0; ks < GBK / 16; ks++) {     // 4 k16 steps
            const int kk = ks * 8;                  // u32 col offset
            uint32_t af[4][4], bf[4][2];
#pragma unroll
            for (int mi = 0; mi < 4; mi++) {
                int r0 = arow0 + mi * 16 * GLD + kk;
                af[mi][0] = asu[r0];
                af[mi][1] = asu[r0 + 8 * GLD];
                af[mi][2] = asu[r0 + 4];
                af[mi][3] = asu[r0 + 8 * GLD + 4];
            }
#pragma unroll
            for (int ni = 0; ni < 4; ni++) {
                int c0 = brow0 + ni * 8 * GLD + kk;
                bf[ni][0] = bsu[c0];
                bf[ni][1] = bsu[c0 + 4];
            }
#pragma unroll
            for (int mi = 0; mi < 4; mi++)
#pragma unroll
                for (int ni = 0; ni < 4; ni++)
                    mma_fp16(acc[mi][ni], af[mi], bf[ni]);
        }
    }

    // epilogue
    const int mb = blockIdx.y * GBM + wm * 64;
    const int nb = blockIdx.x * GBN + wn * 32;
    float*  C32b = (OUT32) ? (C + bz * sC)   : nullptr;
    __half* C16b = (OUT16) ? (C16 + bz * sC) : nullptr;

#pragma unroll
    for (int mi = 0; mi < 4; mi++) {
        int row = mb + mi * 16 + g;
#pragma unroll
        for (int ni = 0; ni < 4; ni++) {
            int col = nb + ni * 8 + 2 * tq;
            float v0 = alpha * acc[mi][ni][0];
            float v1 = alpha * acc[mi][ni][1];
            float v2 = alpha * acc[mi][ni][2];
            float v3 = alpha * acc[mi][ni][3];
            if (bias != nullptr) {
                float b0 = bias[col], b1 = bias[col + 1];
                v0 += b0; v1 += b1; v2 += b0; v3 += b1;
            }
            if (ACT == 1) {
                v0 = gelu_tanh_f(v0); v1 = gelu_tanh_f(v1);
                v2 = gelu_tanh_f(v2); v3 = gelu_tanh_f(v3);
            }
            if (OUT32) {
                *(float2*)(C32b + (long long)row * ldc + col)       = make_float2(v0, v1);
                *(float2*)(C32b + (long long)(row + 8) * ldc + col) = make_float2(v2, v3);
            }
            if (OUT16) {
                *(__half2*)(C16b + (long long)row * ldc + col)       = __floats2half2_rn(v0, v1);
                *(__half2*)(C16b + (long long)(row + 8) * ldc + col) = __floats2half2_rn(v2, v3);
            }
        }
    }
}

// ---------------------------------------------------------------------------
// fp32 -> fp16 conversion (weights), n % 4 == 0
// ---------------------------------------------------------------------------
__global__ void f32_to_f16_kernel(const float* __restrict__ src, __half* __restrict__ dst,
                                  long long n)
{
    long long i = ((long long)blockIdx.x * blockDim.x + threadIdx.x) * 4;
    long long stride = (long long)gridDim.x * blockDim.x * 4;
    for (; i < n; i += stride) {
        float4 v = *(const float4*)(src + i);
        __half2 h0 = __floats2half2_rn(v.x, v.y);
        __half2 h1 = __floats2half2_rn(v.z, v.w);
        *(__half2*)(dst + i)     = h0;
        *(__half2*)(dst + i + 2) = h1;
    }
}

// ---------------------------------------------------------------------------
// LayerNorm + modulation -> fp16:  out = shift + (1+scale) * LN(x)
// ---------------------------------------------------------------------------
__global__ void ln_mod_kernel(const float* __restrict__ x, const float* __restrict__ mod,
                              __half* __restrict__ out)
{
    const int t = blockIdx.x;
    const float* xr = x + (size_t)t * HIDDEN;
    __half* orow = out + (size_t)t * HIDDEN;

    float s = 0.f, s2 = 0.f;
    for (int c = threadIdx.x; c < HIDDEN; c += 256) {
        float v = xr[c];
        s += v; s2 += v * v;
    }
    const int lane = threadIdx.x & 31, wid = threadIdx.x >> 5;
#pragma unroll
    for (int o = 16; o > 0; o >>= 1) {
        s  += __shfl_xor_sync(0xffffffffu, s, o);
        s2 += __shfl_xor_sync(0xffffffffu, s2, o);
    }
    __shared__ float sh[16];
    if (lane == 0) { sh[wid] = s; sh[8 + wid] = s2; }
    __syncthreads();
    float S = 0.f, S2 = 0.f;
#pragma unroll
    for (int w = 0; w < 8; w++) { S += sh[w]; S2 += sh[8 + w]; }
    float mean = S * (1.0f / HIDDEN);
    float var  = S2 * (1.0f / HIDDEN) - mean * mean;
    float inv  = rsqrtf(var + 1e-6f);

    for (int c = threadIdx.x; c < HIDDEN; c += 256) {
        float v = mod[c] + (1.0f + mod[HIDDEN + c]) * ((xr[c] - mean) * inv);
        orow[c] = __float2half_rn(v);
    }
}

// ---------------------------------------------------------------------------
// Per-(token, head): RMS norm q/k, RoPE, scatter fp16 q/k [h][l][d], vT [h][d][l]
// ---------------------------------------------------------------------------
__global__ void rmsrope_kernel(const float* __restrict__ qkv,
                               const float* __restrict__ q_scale,
                               const float* __restrict__ k_scale,
                               const float* __restrict__ pe,
                               __half* __restrict__ qo, __half* __restrict__ ko,
                               __half* __restrict__ vT, int l_off)
{
    const int t = blockIdx.x, h = blockIdx.y, d = threadIdx.x;
    const int l = l_off + t;
    const float* base = qkv + (size_t)t * (3 * HIDDEN) + h * HEAD_DIM;
    float qv = base[d];
    float kv = base[HIDDEN + d];
    float vv = base[2 * HIDDEN + d];

    const int lane = d & 31, wid = d >> 5;
    float qs = qv * qv, ks = kv * kv;
#pragma unroll
    for (int o = 16; o > 0; o >>= 1) {
        qs += __shfl_xor_sync(0xffffffffu, qs, o);
        ks += __shfl_xor_sync(0xffffffffu, ks, o);
    }
    __shared__ float red[8];
    if (lane == 0) { red[wid] = qs; red[4 + wid] = ks; }
    __syncthreads();
    float qm = (red[0] + red[1] + red[2] + red[3]) * (1.0f / HEAD_DIM);
    float km = (red[4] + red[5] + red[6] + red[7]) * (1.0f / HEAD_DIM);

    float qn = qv * rsqrtf(qm + 1e-6f) * q_scale[d];
    float kn = kv * rsqrtf(km + 1e-6f) * k_scale[d];

    __shared__ float sq[HEAD_DIM], sk[HEAD_DIM];
    sq[d] = qn; sk[d] = kn;
    __syncthreads();

    const int i = d >> 1;
    const float* p4 = pe + ((size_t)l * (HEAD_DIM / 2) + i) * 4;
    float rq, rk;
    if ((d & 1) == 0) {
        rq = p4[0] * sq[d] + p4[1] * sq[d + 1];
        rk = p4[0] * sk[d] + p4[1] * sk[d + 1];
    } else {
        rq = p4[2] * sq[d - 1] + p4[3] * sq[d];
        rk = p4[2] * sk[d - 1] + p4[3] * sk[d];
    }
    size_t qidx = ((size_t)h * SEQ_L + l) * HEAD_DIM + d;
    qo[qidx] = __float2half_rn(rq);
    ko[qidx] = __float2half_rn(rk);
    vT[((size_t)h * HEAD_DIM + d) * SEQ_L + l] = __float2half_rn(vv);
}

// ---------------------------------------------------------------------------
// Row softmax over 2048 columns: fp32 scores in, fp16 probs out
// ---------------------------------------------------------------------------
__global__ void softmax_kernel(const float* __restrict__ s, __half* __restrict__ p16)
{
    const float* p = s + (size_t)blockIdx.x * SEQ_L;
    __half* o = p16 + (size_t)blockIdx.x * SEQ_L;
    float vals[8];
    float m = -1e30f;
#pragma unroll
    for (int i = 0; i < 8; i++) {
        vals[i] = p[threadIdx.x + i * 256];
        m = fmaxf(m, vals[i]);
    }
    const int lane = threadIdx.x & 31, wid = threadIdx.x >> 5;
#pragma unroll
    for (int o2 = 16; o2 > 0; o2 >>= 1) m = fmaxf(m, __shfl_xor_sync(0xffffffffu, m, o2));
    __shared__ float sh[8];
    if (lane == 0) sh[wid] = m;
    __syncthreads();
    float M = sh[0];
#pragma unroll
    for (int w = 1; w < 8; w++) M = fmaxf(M, sh[w]);
    __syncthreads();

    float sum = 0.f;
#pragma unroll
    for (int i = 0; i < 8; i++) {
        vals[i] = __expf(vals[i] - M);
        sum += vals[i];
    }
#pragma unroll
    for (int o2 = 16; o2 > 0; o2 >>= 1) sum += __shfl_xor_sync(0xffffffffu, sum, o2);
    if (lane == 0) sh[wid] = sum;
    __syncthreads();
    float S = 0.f;
#pragma unroll
    for (int w = 0; w < 8; w++) S += sh[w];
    float inv = 1.0f / S;
#pragma unroll
    for (int i = 0; i < 8; i++) o[threadIdx.x + i * 256] = __float2half_rn(vals[i] * inv);
}

// ---------------------------------------------------------------------------
// Gated residual: out = base + gate[c] * delta   (optional final clip)
// ---------------------------------------------------------------------------
template<bool CLIP>
__global__ void residual_kernel(const float* __restrict__ base, const float* __restrict__ delta,
                                const float* __restrict__ gate, float* __restrict__ out, int n)
{
    for (int i = blockIdx.x * blockDim.x + threadIdx.x; i < n; i += gridDim.x * blockDim.x) {
        float v = base[i] + gate[i % HIDDEN] * delta[i];
        if (CLIP) v = fminf(fmaxf(v, -65504.0f), 65504.0f);
        out[i] = v;
    }
}

// ---------------------------------------------------------------------------
// Host launcher
// ---------------------------------------------------------------------------
static void launch_gemm(const __half* A, const __half* B, const float* bias,
                        float* C, __half* C16,
                        int M, int N, int K, int lda, int ldb, int ldc,
                        long long sA, long long sB, long long sC,
                        int batch, float alpha, int act, int out32, int out16)
{
    dim3 grid(N / GBN, M / GBM, batch), block(256);
    if (act == 0 && out32 && !out16)
        gemm_fp16<0,1,0><<<grid, block, GEMM_SMEM>>>(A, B, bias, C, C16, K, lda, ldb, ldc, sA, sB, sC, alpha);
    else if (act == 1 && !out32 && out16)
        gemm_fp16<1,0,1><<<grid, block, GEMM_SMEM>>>(A, B, bias, C, C16, K, lda, ldb, ldc, sA, sB, sC, alpha);
    else
        gemm_fp16<0,0,1><<<grid, block, GEMM_SMEM>>>(A, B, bias, C, C16, K, lda, ldb, ldc, sA, sB, sC, alpha);
}

static void conv_w(const float* src, __half* dst, long long n)
{
    f32_to_f16_kernel<<<1024, 256>>>(src, dst, n);
}

extern "C" void kernel_launch(void* const* d_in, const int* in_sizes, int n_in,
                              void* d_out, int out_size)
{
    static bool attr_done = false;
    if (!attr_done) {
        cudaFuncSetAttribute(gemm_fp16<0,1,0>, cudaFuncAttributeMaxDynamicSharedMemorySize, GEMM_SMEM);
        cudaFuncSetAttribute(gemm_fp16<1,0,1>, cudaFuncAttributeMaxDynamicSharedMemorySize, GEMM_SMEM);
        cudaFuncSetAttribute(gemm_fp16<0,0,1>, cudaFuncAttributeMaxDynamicSharedMemorySize, GEMM_SMEM);
        attr_done = true;
    }

    const float* img         = (const float*)d_in[0];
    const float* txt         = (const float*)d_in[1];
    const float* img_mod1    = (const float*)d_in[2];
    const float* img_mod2    = (const float*)d_in[3];
    const float* txt_mod1    = (const float*)d_in[4];
    const float* txt_mod2    = (const float*)d_in[5];
    const float* img_qkv_w   = (const float*)d_in[6];
    const float* img_qkv_b   = (const float*)d_in[7];
    const float* img_q_scale = (const float*)d_in[8];
    const float* img_k_scale = (const float*)d_in[9];
    const float* img_proj_w  = (const float*)d_in[10];
    const float* img_proj_b  = (const float*)d_in[11];
    const float* img_mlp_w1  = (const float*)d_in[12];
    const float* img_mlp_b1  = (const float*)d_in[13];
    const float* img_mlp_w2  = (const float*)d_in[14];
    const float* img_mlp_b2  = (const float*)d_in[15];
    const float* txt_qkv_w   = (const float*)d_in[16];
    const float* txt_qkv_b   = (const float*)d_in[17];
    const float* txt_q_scale = (const float*)d_in[18];
    const float* txt_k_scale = (const float*)d_in[19];
    const float* txt_proj_w  = (const float*)d_in[20];
    const float* txt_proj_b  = (const float*)d_in[21];
    const float* txt_mlp_w1  = (const float*)d_in[22];
    const float* txt_mlp_b1  = (const float*)d_in[23];
    const float* txt_mlp_w2  = (const float*)d_in[24];
    const float* txt_mlp_b2  = (const float*)d_in[25];
    const float* pe          = (const float*)d_in[26];

    __half *xm16, *q16, *k16, *vT16, *probs16, *attn16, *h16;
    __half *wiq, *wtq, *wip, *wtp, *wim1, *wim2, *wtm1, *wtm2;
    float *qkv_i, *qkv_t, *scores, *tmp;
    cudaGetSymbolAddress((void**)&xm16, g_xm16);
    cudaGetSymbolAddress((void**)&qkv_i, g_qkv_img);
    cudaGetSymbolAddress((void**)&qkv_t, g_qkv_txt);
    cudaGetSymbolAddress((void**)&q16, g_q16);
    cudaGetSymbolAddress((void**)&k16, g_k16);
    cudaGetSymbolAddress((void**)&vT16, g_vT16);
    cudaGetSymbolAddress((void**)&scores, g_scores);
    cudaGetSymbolAddress((void**)&probs16, g_probs16);
    cudaGetSymbolAddress((void**)&attn16, g_attn16);
    cudaGetSymbolAddress((void**)&tmp, g_tmp);
    cudaGetSymbolAddress((void**)&h16, g_h16);
    cudaGetSymbolAddress((void**)&wiq, w16_img_qkv);
    cudaGetSymbolAddress((void**)&wtq, w16_txt_qkv);
    cudaGetSymbolAddress((void**)&wip, w16_img_proj);
    cudaGetSymbolAddress((void**)&wtp, w16_txt_proj);
    cudaGetSymbolAddress((void**)&wim1, w16_img_mlp1);
    cudaGetSymbolAddress((void**)&wim2, w16_img_mlp2);
    cudaGetSymbolAddress((void**)&wtm1, w16_txt_mlp1);
    cudaGetSymbolAddress((void**)&wtm2, w16_txt_mlp2);

    float* out_img = (float*)d_out;
    float* out_txt = out_img + (size_t)T_IMG * HIDDEN;

    const float attn_scale = 0.08838834764831845f;  // 1/sqrt(128)

    // ---- weight conversions (fp32 -> fp16) ----
    conv_w(img_qkv_w, wiq, (long long)3 * HIDDEN * HIDDEN);
    conv_w(txt_qkv_w, wtq, (long long)3 * HIDDEN * HIDDEN);
    conv_w(img_proj_w, wip, (long long)HIDDEN * HIDDEN);
    conv_w(txt_proj_w, wtp, (long long)HIDDEN * HIDDEN);
    conv_w(img_mlp_w1, wim1, (long long)MLPD * HIDDEN);
    conv_w(img_mlp_w2, wim2, (long long)HIDDEN * MLPD);
    conv_w(txt_mlp_w1, wtm1, (long long)MLPD * HIDDEN);
    conv_w(txt_mlp_w2, wtm2, (long long)HIDDEN * MLPD);

    // ---- QKV for both streams ----
    ln_mod_kernel<<<T_IMG, 256>>>(img, img_mod1, xm16);
    launch_gemm(xm16, wiq, img_qkv_b, qkv_i, nullptr, T_IMG, 3 * HIDDEN, HIDDEN,
                HIDDEN, HIDDEN, 3 * HIDDEN, 0, 0, 0, 1, 1.0f, 0, 1, 0);
    ln_mod_kernel<<<T_TXT, 256>>>(txt, txt_mod1, xm16);
    launch_gemm(xm16, wtq, txt_qkv_b, qkv_t, nullptr, T_TXT, 3 * HIDDEN, HIDDEN,
                HIDDEN, HIDDEN, 3 * HIDDEN, 0, 0, 0, 1, 1.0f, 0, 1, 0);

    // ---- RMS norm + RoPE + scatter (txt tokens: l in [0,512), img [512,2048)) ----
    rmsrope_kernel<<<dim3(T_TXT, NUM_HEADS), HEAD_DIM>>>(qkv_t, txt_q_scale, txt_k_scale, pe, q16, k16, vT16, 0);
    rmsrope_kernel<<<dim3(T_IMG, NUM_HEADS), HEAD_DIM>>>(qkv_i, img_q_scale, img_k_scale, pe, q16, k16, vT16, T_TXT);

    // ---- Attention ----
    launch_gemm(q16, k16, nullptr, scores, nullptr, SEQ_L, SEQ_L, HEAD_DIM,
                HEAD_DIM, HEAD_DIM, SEQ_L,
                (long long)SEQ_L * HEAD_DIM, (long long)SEQ_L * HEAD_DIM,
                (long long)SEQ_L * SEQ_L, NUM_HEADS, attn_scale, 0, 1, 0);
    softmax_kernel<<<NUM_HEADS * SEQ_L, 256>>>(scores, probs16);
    launch_gemm(probs16, vT16, nullptr, nullptr, attn16, SEQ_L, HEAD_DIM, SEQ_L,
                SEQ_L, SEQ_L, HIDDEN,
                (long long)SEQ_L * SEQ_L, (long long)HEAD_DIM * SEQ_L,
                (long long)HEAD_DIM, NUM_HEADS, 1.0f, 0, 0, 1);

    // ---- Attention projections + gated residuals ----
    launch_gemm(attn16 + (size_t)T_TXT * HIDDEN, wip, img_proj_b, tmp, nullptr,
                T_IMG, HIDDEN, HIDDEN, HIDDEN, HIDDEN, HIDDEN, 0, 0, 0, 1, 1.0f, 0, 1, 0);
    residual_kernel<false><<<4096, 256>>>(img, tmp, img_mod1 + 2 * HIDDEN, out_img, T_IMG * HIDDEN);

    launch_gemm(attn16, wtp, txt_proj_b, tmp, nullptr,
                T_TXT, HIDDEN, HIDDEN, HIDDEN, HIDDEN, HIDDEN, 0, 0, 0, 1, 1.0f, 0, 1, 0);
    residual_kernel<false><<<2048, 256>>>(txt, tmp, txt_mod1 + 2 * HIDDEN, out_txt, T_TXT * HIDDEN);

    // ---- img MLP ----
    ln_mod_kernel<<<T_IMG, 256>>>(out_img, img_mod2, xm16);
    launch_gemm(xm16, wim1, img_mlp_b1, nullptr, h16, T_IMG, MLPD, HIDDEN,
                HIDDEN, HIDDEN, MLPD, 0, 0, 0, 1, 1.0f, 1, 0, 1);
    launch_gemm(h16, wim2, img_mlp_b2, tmp, nullptr, T_IMG, HIDDEN, MLPD,
                MLPD, MLPD, HIDDEN, 0, 0, 0, 1, 1.0f, 0, 1, 0);
    residual_kernel<false><<<4096, 256>>>(out_img, tmp, img_mod2 + 2 * HIDDEN, out_img, T_IMG * HIDDEN);

    // ---- txt MLP (final residual fused with clip) ----
    ln_mod_kernel<<<T_TXT, 256>>>(out_txt, txt_mod2, xm16);
    launch_gemm(xm16, wtm1, txt_mlp_b1, nullptr, h16, T_TXT, MLPD, HIDDEN,
                HIDDEN, HIDDEN, MLPD, 0, 0, 0, 1, 1.0f, 1, 0, 1);
    launch_gemm(h16, wtm2, txt_mlp_b2, tmp, nullptr, T_TXT, HIDDEN, MLPD,
                MLPD, MLPD, HIDDEN, 0, 0, 0, 1, 1.0f, 0, 1, 0);
    residual_kernel<true><<<2048, 256>>>(out_txt, tmp, txt_mod2 + 2 * HIDDEN, out_txt, T_TXT * HIDDEN);
}

// round 17
// speedup vs baseline: 2.1799x; 1.0189x over previous
#include <cuda_runtime.h>
#include <cuda_fp16.h>
#include <cstdint>
#include <cstdio>

// ---------------------------------------------------------------------------
// Problem constants
// ---------------------------------------------------------------------------
#define NUM_HEADS 24
#define HEAD_DIM  128
#define HIDDEN    3072
#define MLPD      12288
#define T_IMG     1536
#define T_TXT     512
#define SEQ_L     2048   // T_IMG + T_TXT

// ---------------------------------------------------------------------------
// Scratch (device globals; allocation-free per harness rules).
// All fp16 buffers 16B-aligned for cp.async / vector access.
// ---------------------------------------------------------------------------
__device__ __align__(16) __half g_xm16[(size_t)T_IMG * HIDDEN];
__device__ float  g_qkv_img[(size_t)T_IMG * 3 * HIDDEN];
__device__ float  g_qkv_txt[(size_t)T_TXT * 3 * HIDDEN];
__device__ __align__(16) __half g_q16[(size_t)NUM_HEADS * SEQ_L * HEAD_DIM];
__device__ __align__(16) __half g_k16[(size_t)NUM_HEADS * SEQ_L * HEAD_DIM];
__device__ __align__(16) __half g_vT16[(size_t)NUM_HEADS * HEAD_DIM * SEQ_L];
__device__ float  g_scores[(size_t)NUM_HEADS * SEQ_L * SEQ_L];    // 402 MB
__device__ __align__(16) __half g_probs16[(size_t)NUM_HEADS * SEQ_L * SEQ_L];   // 201 MB
__device__ __align__(16) __half g_attn16[(size_t)SEQ_L * HIDDEN];
__device__ float  g_tmp[(size_t)T_IMG * HIDDEN];
__device__ __align__(16) __half g_h16[(size_t)T_IMG * MLPD];

// fp16 weights (converted once per launch)
__device__ __align__(16) __half w16_img_qkv[(size_t)3 * HIDDEN * HIDDEN];
__device__ __align__(16) __half w16_txt_qkv[(size_t)3 * HIDDEN * HIDDEN];
__device__ __align__(16) __half w16_img_proj[(size_t)HIDDEN * HIDDEN];
__device__ __align__(16) __half w16_txt_proj[(size_t)HIDDEN * HIDDEN];
__device__ __align__(16) __half w16_img_mlp1[(size_t)MLPD * HIDDEN];
__device__ __align__(16) __half w16_img_mlp2[(size_t)HIDDEN * MLPD];
__device__ __align__(16) __half w16_txt_mlp1[(size_t)MLPD * HIDDEN];
__device__ __align__(16) __half w16_txt_mlp2[(size_t)HIDDEN * MLPD];

// ---------------------------------------------------------------------------
// Helpers
// ---------------------------------------------------------------------------
__device__ __forceinline__ void mma_fp16(float* d, const uint32_t* a, const uint32_t* b) {
    asm volatile(
        "mma.sync.aligned.m16n8k16.row.col.f32.f16.f16.f32 "
        "{%0,%1,%2,%3}, {%4,%5,%6,%7}, {%8,%9}, {%0,%1,%2,%3};\n"
        : "+f"(d[0]), "+f"(d[1]), "+f"(d[2]), "+f"(d[3])
        : "r"(a[0]), "r"(a[1]), "r"(a[2]), "r"(a[3]), "r"(b[0]), "r"(b[1]));
}

__device__ __forceinline__ void ldsm_x4(uint32_t& r0, uint32_t& r1, uint32_t& r2, uint32_t& r3,
                                        uint32_t saddr) {
    asm volatile("ldmatrix.sync.aligned.m8n8.x4.shared.b16 {%0,%1,%2,%3}, [%4];"
                 : "=r"(r0), "=r"(r1), "=r"(r2), "=r"(r3) : "r"(saddr));
}

__device__ __forceinline__ void cp_async16(uint32_t saddr, const void* gaddr) {
    asm volatile("cp.async.ca.shared.global [%0], [%1], 16;\n" :: "r"(saddr), "l"(gaddr));
}
__device__ __forceinline__ void cp_commit() {
    asm volatile("cp.async.commit_group;\n" ::: "memory");
}
template<int N>
__device__ __forceinline__ void cp_wait() {
    asm volatile("cp.async.wait_group %0;\n" :: "n"(N) : "memory");
}

__device__ __forceinline__ float gelu_tanh_f(float x) {
    float x3 = x * x * x;
    return 0.5f * x * (1.0f + tanhf(0.7978845608028654f * (x + 0.044715f * x3)));
}

// ---------------------------------------------------------------------------
// fp16 MMA GEMM, 3-stage cp.async pipeline, 256 threads (8 warps),
// 128x128x64(fp16) block tile, 64x32 warp tile (2x4 warp grid), ldmatrix
// fragment loads (6 LDSM.x4 per k16 step instead of 24 LDS.32):
//   C[M,N] = act(alpha * A[M,K] @ B[N,K]^T + bias)
// A, B are fp16 in gmem. Outputs: fp32 C (if OUT32), fp16 C16 (if OUT16).
// M%128==0, N%128==0, K%64==0, lda/ldb %8==0.
// Batched via blockIdx.z with element strides sA, sB, sC.
// Row stride GLD=36 u32 (144 B): 16B-aligned; LDSM 8-row phases hit banks
// {4i..4i+3} mod 32 -> conflict-free.
// ---------------------------------------------------------------------------
#define GBM 128
#define GBN 128
#define GBK 64                          // fp16 K elements per tile (128B rows)
#define GLD 36                          // u32 stride per row (32 data + 4 pad)
#define NSTG 3
#define STAGE_U32 (2 * GBM * GLD)       // A + B tiles = 9216 u32 = 36864 B
#define GEMM_SMEM (NSTG * STAGE_U32 * 4)  // 110592 bytes

template<int ACT, int OUT32, int OUT16>
__global__ void __launch_bounds__(256, 1)
gemm_fp16(const __half* __restrict__ A, const __half* __restrict__ B,
          const float* __restrict__ bias, float* __restrict__ C,
          __half* __restrict__ C16,
          int K, int lda, int ldb, int ldc,
          long long sA, long long sB, long long sC, float alpha)
{
    extern __shared__ uint32_t smem[];
    const uint32_t sbase = (uint32_t)__cvta_generic_to_shared(smem);

    const int tid  = threadIdx.x;
    const int lane = tid & 31;
    const int warp = tid >> 5;
    const int wm = warp & 1;          // 2 warps in M -> 64 rows each
    const int wn = warp >> 1;         // 4 warps in N -> 32 cols each
    const int g  = lane >> 2;         // 0..7
    const int tq = lane & 3;          // 0..3

    const long long bz = blockIdx.z;
    const __half* Ab = A + bz * sA + (long long)(blockIdx.y * GBM) * lda;
    const __half* Bb = B + bz * sB + (long long)(blockIdx.x * GBN) * ldb;

    // cp.async: per matrix per stage 128 rows x 8 chunks(16B) = 1024; 4/thread
    const int crow = tid >> 3;          // 0..31
    const int cch  = tid & 7;           // chunk col 0..7
    const int ccolh = cch * 8;          // fp16 col
    const int ccolu = cch * 4;          // u32 col

    const int ntiles = K / GBK;

    auto load_stage = [&](int stage, int kt) {
        const uint32_t sa = sbase + (uint32_t)(stage * STAGE_U32) * 4u;
        const uint32_t sb = sa + (uint32_t)(GBM * GLD) * 4u;
        const int koff = kt * GBK + ccolh;
#pragma unroll
        for (int i = 0; i < 4; i++) {
            int r = crow + 32 * i;
            cp_async16(sa + (uint32_t)(r * GLD + ccolu) * 4u, Ab + (long long)r * lda + koff);
            cp_async16(sb + (uint32_t)(r * GLD + ccolu) * 4u, Bb + (long long)r * ldb + koff);
        }
    };

    float acc[4][4][4];
#pragma unroll
    for (int a = 0; a < 4; a++)
#pragma unroll
        for (int b = 0; b < 4; b++)
#pragma unroll
            for (int r = 0; r < 4; r++) acc[a][b][r] = 0.0f;

#pragma unroll
    for (int s = 0; s < NSTG - 1; s++) {
        if (s < ntiles) load_stage(s, s);
        cp_commit();
    }

    // ldmatrix per-lane address components
    const int a_lrow = lane & 15;               // row within 16-row A submtx group
    const int a_kadd = (lane >> 4) << 2;        // +4 u32 (k+8) for lanes 16..31
    const int b_lrow = (lane & 7) + ((lane & 16) >> 1);  // row within 16-row B group
    const int b_kadd = (lane & 8) >> 1;         // +4 u32 (k+8) for lanes 8-15, 24-31

    // fixed (stage-relative) u32 offsets
    const int a_off0 = (wm * 64 + a_lrow) * GLD + a_kadd;   // + mi*16*GLD + kk
    const int b_off0 = (wn * 32 + b_lrow) * GLD + b_kadd;   // + ni2*16*GLD + kk

    for (int kt = 0; kt < ntiles; kt++) {
        cp_wait<NSTG - 2>();
        __syncthreads();

        if (kt + NSTG - 1 < ntiles) load_stage((kt + NSTG - 1) % NSTG, kt + NSTG - 1);
        cp_commit();

        const uint32_t stg_a = sbase + (uint32_t)((kt % NSTG) * STAGE_U32) * 4u;
        const uint32_t stg_b = stg_a + (uint32_t)(GBM * GLD) * 4u;

#pragma unroll
        for (int ks = 0; ks < GBK / 16; ks++) {     // 4 k16 steps
            const int kk = ks * 8;                  // u32 col offset
            uint32_t af[4][4], bf[4][2];
#pragma unroll
            for (int mi = 0; mi < 4; mi++) {
                uint32_t ad = stg_a + (uint32_t)(a_off0 + mi * 16 * GLD + kk) * 4u;
                ldsm_x4(af[mi][0], af[mi][1], af[mi][2], af[mi][3], ad);
            }
#pragma unroll
            for (int ni2 = 0; ni2 < 2; ni2++) {
                uint32_t bd = stg_b + (uint32_t)(b_off0 + ni2 * 16 * GLD + kk) * 4u;
                ldsm_x4(bf[2 * ni2][0], bf[2 * ni2][1], bf[2 * ni2 + 1][0], bf[2 * ni2 + 1][1], bd);
            }
#pragma unroll
            for (int mi = 0; mi < 4; mi++)
#pragma unroll
                for (int ni = 0; ni < 4; ni++)
                    mma_fp16(acc[mi][ni], af[mi], bf[ni]);
        }
    }

    // epilogue
    const int mb = blockIdx.y * GBM + wm * 64;
    const int nb = blockIdx.x * GBN + wn * 32;
    float*  C32b = (OUT32) ? (C + bz * sC)   : nullptr;
    __half* C16b = (OUT16) ? (C16 + bz * sC) : nullptr;

#pragma unroll
    for (int mi = 0; mi < 4; mi++) {
        int row = mb + mi * 16 + g;
#pragma unroll
        for (int ni = 0; ni < 4; ni++) {
            int col = nb + ni * 8 + 2 * tq;
            float v0 = alpha * acc[mi][ni][0];
            float v1 = alpha * acc[mi][ni][1];
            float v2 = alpha * acc[mi][ni][2];
            float v3 = alpha * acc[mi][ni][3];
            if (bias != nullptr) {
                float b0 = bias[col], b1 = bias[col + 1];
                v0 += b0; v1 += b1; v2 += b0; v3 += b1;
            }
            if (ACT == 1) {
                v0 = gelu_tanh_f(v0); v1 = gelu_tanh_f(v1);
                v2 = gelu_tanh_f(v2); v3 = gelu_tanh_f(v3);
            }
            if (OUT32) {
                *(float2*)(C32b + (long long)row * ldc + col)       = make_float2(v0, v1);
                *(float2*)(C32b + (long long)(row + 8) * ldc + col) = make_float2(v2, v3);
            }
            if (OUT16) {
                *(__half2*)(C16b + (long long)row * ldc + col)       = __floats2half2_rn(v0, v1);
                *(__half2*)(C16b + (long long)(row + 8) * ldc + col) = __floats2half2_rn(v2, v3);
            }
        }
    }
}

// ---------------------------------------------------------------------------
// fp32 -> fp16 conversion (weights), n % 4 == 0
// ---------------------------------------------------------------------------
__global__ void f32_to_f16_kernel(const float* __restrict__ src, __half* __restrict__ dst,
                                  long long n)
{
    long long i = ((long long)blockIdx.x * blockDim.x + threadIdx.x) * 4;
    long long stride = (long long)gridDim.x * blockDim.x * 4;
    for (; i < n; i += stride) {
        float4 v = *(const float4*)(src + i);
        __half2 h0 = __floats2half2_rn(v.x, v.y);
        __half2 h1 = __floats2half2_rn(v.z, v.w);
        *(__half2*)(dst + i)     = h0;
        *(__half2*)(dst + i + 2) = h1;
    }
}

// ---------------------------------------------------------------------------
// LayerNorm + modulation -> fp16:  out = shift + (1+scale) * LN(x)
// ---------------------------------------------------------------------------
__global__ void ln_mod_kernel(const float* __restrict__ x, const float* __restrict__ mod,
                              __half* __restrict__ out)
{
    const int t = blockIdx.x;
    const float* xr = x + (size_t)t * HIDDEN;
    __half* orow = out + (size_t)t * HIDDEN;

    float s = 0.f, s2 = 0.f;
    for (int c = threadIdx.x; c < HIDDEN; c += 256) {
        float v = xr[c];
        s += v; s2 += v * v;
    }
    const int lane = threadIdx.x & 31, wid = threadIdx.x >> 5;
#pragma unroll
    for (int o = 16; o > 0; o >>= 1) {
        s  += __shfl_xor_sync(0xffffffffu, s, o);
        s2 += __shfl_xor_sync(0xffffffffu, s2, o);
    }
    __shared__ float sh[16];
    if (lane == 0) { sh[wid] = s; sh[8 + wid] = s2; }
    __syncthreads();
    float S = 0.f, S2 = 0.f;
#pragma unroll
    for (int w = 0; w < 8; w++) { S += sh[w]; S2 += sh[8 + w]; }
    float mean = S * (1.0f / HIDDEN);
    float var  = S2 * (1.0f / HIDDEN) - mean * mean;
    float inv  = rsqrtf(var + 1e-6f);

    for (int c = threadIdx.x; c < HIDDEN; c += 256) {
        float v = mod[c] + (1.0f + mod[HIDDEN + c]) * ((xr[c] - mean) * inv);
        orow[c] = __float2half_rn(v);
    }
}

// ---------------------------------------------------------------------------
// Per-(token, head): RMS norm q/k, RoPE, scatter fp16 q/k [h][l][d], vT [h][d][l]
// ---------------------------------------------------------------------------
__global__ void rmsrope_kernel(const float* __restrict__ qkv,
                               const float* __restrict__ q_scale,
                               const float* __restrict__ k_scale,
                               const float* __restrict__ pe,
                               __half* __restrict__ qo, __half* __restrict__ ko,
                               __half* __restrict__ vT, int l_off)
{
    const int t = blockIdx.x, h = blockIdx.y, d = threadIdx.x;
    const int l = l_off + t;
    const float* base = qkv + (size_t)t * (3 * HIDDEN) + h * HEAD_DIM;
    float qv = base[d];
    float kv = base[HIDDEN + d];
    float vv = base[2 * HIDDEN + d];

    const int lane = d & 31, wid = d >> 5;
    float qs = qv * qv, ks = kv * kv;
#pragma unroll
    for (int o = 16; o > 0; o >>= 1) {
        qs += __shfl_xor_sync(0xffffffffu, qs, o);
        ks += __shfl_xor_sync(0xffffffffu, ks, o);
    }
    __shared__ float red[8];
    if (lane == 0) { red[wid] = qs; red[4 + wid] = ks; }
    __syncthreads();
    float qm = (red[0] + red[1] + red[2] + red[3]) * (1.0f / HEAD_DIM);
    float km = (red[4] + red[5] + red[6] + red[7]) * (1.0f / HEAD_DIM);

    float qn = qv * rsqrtf(qm + 1e-6f) * q_scale[d];
    float kn = kv * rsqrtf(km + 1e-6f) * k_scale[d];

    __shared__ float sq[HEAD_DIM], sk[HEAD_DIM];
    sq[d] = qn; sk[d] = kn;
    __syncthreads();

    const int i = d >> 1;
    const float* p4 = pe + ((size_t)l * (HEAD_DIM / 2) + i) * 4;
    float rq, rk;
    if ((d & 1) == 0) {
        rq = p4[0] * sq[d] + p4[1] * sq[d + 1];
        rk = p4[0] * sk[d] + p4[1] * sk[d + 1];
    } else {
        rq = p4[2] * sq[d - 1] + p4[3] * sq[d];
        rk = p4[2] * sk[d - 1] + p4[3] * sk[d];
    }
    size_t qidx = ((size_t)h * SEQ_L + l) * HEAD_DIM + d;
    qo[qidx] = __float2half_rn(rq);
    ko[qidx] = __float2half_rn(rk);
    vT[((size_t)h * HEAD_DIM + d) * SEQ_L + l] = __float2half_rn(vv);
}

// ---------------------------------------------------------------------------
// Row softmax over 2048 columns: fp32 scores in, fp16 probs out
// ---------------------------------------------------------------------------
__global__ void softmax_kernel(const float* __restrict__ s, __half* __restrict__ p16)
{
    const float* p = s + (size_t)blockIdx.x * SEQ_L;
    __half* o = p16 + (size_t)blockIdx.x * SEQ_L;
    float vals[8];
    float m = -1e30f;
#pragma unroll
    for (int i = 0; i < 8; i++) {
        vals[i] = p[threadIdx.x + i * 256];
        m = fmaxf(m, vals[i]);
    }
    const int lane = threadIdx.x & 31, wid = threadIdx.x >> 5;
#pragma unroll
    for (int o2 = 16; o2 > 0; o2 >>= 1) m = fmaxf(m, __shfl_xor_sync(0xffffffffu, m, o2));
    __shared__ float sh[8];
    if (lane == 0) sh[wid] = m;
    __syncthreads();
    float M = sh[0];
#pragma unroll
    for (int w = 1; w < 8; w++) M = fmaxf(M, sh[w]);
    __syncthreads();

    float sum = 0.f;
#pragma unroll
    for (int i = 0; i < 8; i++) {
        vals[i] = __expf(vals[i] - M);
        sum += vals[i];
    }
#pragma unroll
    for (int o2 = 16; o2 > 0; o2 >>= 1) sum += __shfl_xor_sync(0xffffffffu, sum, o2);
    if (lane == 0) sh[wid] = sum;
    __syncthreads();
    float S = 0.f;
#pragma unroll
    for (int w = 0; w < 8; w++) S += sh[w];
    float inv = 1.0f / S;
#pragma unroll
    for (int i = 0; i < 8; i++) o[threadIdx.x + i * 256] = __float2half_rn(vals[i] * inv);
}

// ---------------------------------------------------------------------------
// Gated residual: out = base + gate[c] * delta   (optional final clip)
// ---------------------------------------------------------------------------
template<bool CLIP>
__global__ void residual_kernel(const float* __restrict__ base, const float* __restrict__ delta,
                                const float* __restrict__ gate, float* __restrict__ out, int n)
{
    for (int i = blockIdx.x * blockDim.x + threadIdx.x; i < n; i += gridDim.x * blockDim.x) {
        float v = base[i] + gate[i % HIDDEN] * delta[i];
        if (CLIP) v = fminf(fmaxf(v, -65504.0f), 65504.0f);
        out[i] = v;
    }
}

// ---------------------------------------------------------------------------
// Host launcher
// ---------------------------------------------------------------------------
static void launch_gemm(const __half* A, const __half* B, const float* bias,
                        float* C, __half* C16,
                        int M, int N, int K, int lda, int ldb, int ldc,
                        long long sA, long long sB, long long sC,
                        int batch, float alpha, int act, int out32, int out16)
{
    dim3 grid(N / GBN, M / GBM, batch), block(256);
    if (act == 0 && out32 && !out16)
        gemm_fp16<0,1,0><<<grid, block, GEMM_SMEM>>>(A, B, bias, C, C16, K, lda, ldb, ldc, sA, sB, sC, alpha);
    else if (act == 1 && !out32 && out16)
        gemm_fp16<1,0,1><<<grid, block, GEMM_SMEM>>>(A, B, bias, C, C16, K, lda, ldb, ldc, sA, sB, sC, alpha);
    else
        gemm_fp16<0,0,1><<<grid, block, GEMM_SMEM>>>(A, B, bias, C, C16, K, lda, ldb, ldc, sA, sB, sC, alpha);
}

static void conv_w(const float* src, __half* dst, long long n)
{
    f32_to_f16_kernel<<<1024, 256>>>(src, dst, n);
}

extern "C" void kernel_launch(void* const* d_in, const int* in_sizes, int n_in,
                              void* d_out, int out_size)
{
    static bool attr_done = false;
    if (!attr_done) {
        cudaFuncSetAttribute(gemm_fp16<0,1,0>, cudaFuncAttributeMaxDynamicSharedMemorySize, GEMM_SMEM);
        cudaFuncSetAttribute(gemm_fp16<1,0,1>, cudaFuncAttributeMaxDynamicSharedMemorySize, GEMM_SMEM);
        cudaFuncSetAttribute(gemm_fp16<0,0,1>, cudaFuncAttributeMaxDynamicSharedMemorySize, GEMM_SMEM);
        attr_done = true;
    }

    const float* img         = (const float*)d_in[0];
    const float* txt         = (const float*)d_in[1];
    const float* img_mod1    = (const float*)d_in[2];
    const float* img_mod2    = (const float*)d_in[3];
    const float* txt_mod1    = (const float*)d_in[4];
    const float* txt_mod2    = (const float*)d_in[5];
    const float* img_qkv_w   = (const float*)d_in[6];
    const float* img_qkv_b   = (const float*)d_in[7];
    const float* img_q_scale = (const float*)d_in[8];
    const float* img_k_scale = (const float*)d_in[9];
    const float* img_proj_w  = (const float*)d_in[10];
    const float* img_proj_b  = (const float*)d_in[11];
    const float* img_mlp_w1  = (const float*)d_in[12];
    const float* img_mlp_b1  = (const float*)d_in[13];
    const float* img_mlp_w2  = (const float*)d_in[14];
    const float* img_mlp_b2  = (const float*)d_in[15];
    const float* txt_qkv_w   = (const float*)d_in[16];
    const float* txt_qkv_b   = (const float*)d_in[17];
    const float* txt_q_scale = (const float*)d_in[18];
    const float* txt_k_scale = (const float*)d_in[19];
    const float* txt_proj_w  = (const float*)d_in[20];
    const float* txt_proj_b  = (const float*)d_in[21];
    const float* txt_mlp_w1  = (const float*)d_in[22];
    const float* txt_mlp_b1  = (const float*)d_in[23];
    const float* txt_mlp_w2  = (const float*)d_in[24];
    const float* txt_mlp_b2  = (const float*)d_in[25];
    const float* pe          = (const float*)d_in[26];

    __half *xm16, *q16, *k16, *vT16, *probs16, *attn16, *h16;
    __half *wiq, *wtq, *wip, *wtp, *wim1, *wim2, *wtm1, *wtm2;
    float *qkv_i, *qkv_t, *scores, *tmp;
    cudaGetSymbolAddress((void**)&xm16, g_xm16);
    cudaGetSymbolAddress((void**)&qkv_i, g_qkv_img);
    cudaGetSymbolAddress((void**)&qkv_t, g_qkv_txt);
    cudaGetSymbolAddress((void**)&q16, g_q16);
    cudaGetSymbolAddress((void**)&k16, g_k16);
    cudaGetSymbolAddress((void**)&vT16, g_vT16);
    cudaGetSymbolAddress((void**)&scores, g_scores);
    cudaGetSymbolAddress((void**)&probs16, g_probs16);
    cudaGetSymbolAddress((void**)&attn16, g_attn16);
    cudaGetSymbolAddress((void**)&tmp, g_tmp);
    cudaGetSymbolAddress((void**)&h16, g_h16);
    cudaGetSymbolAddress((void**)&wiq, w16_img_qkv);
    cudaGetSymbolAddress((void**)&wtq, w16_txt_qkv);
    cudaGetSymbolAddress((void**)&wip, w16_img_proj);
    cudaGetSymbolAddress((void**)&wtp, w16_txt_proj);
    cudaGetSymbolAddress((void**)&wim1, w16_img_mlp1);
    cudaGetSymbolAddress((void**)&wim2, w16_img_mlp2);
    cudaGetSymbolAddress((void**)&wtm1, w16_txt_mlp1);
    cudaGetSymbolAddress((void**)&wtm2, w16_txt_mlp2);

    float* out_img = (float*)d_out;
    float* out_txt = out_img + (size_t)T_IMG * HIDDEN;

    const float attn_scale = 0.08838834764831845f;  // 1/sqrt(128)

    // ---- weight conversions (fp32 -> fp16) ----
    conv_w(img_qkv_w, wiq, (long long)3 * HIDDEN * HIDDEN);
    conv_w(txt_qkv_w, wtq, (long long)3 * HIDDEN * HIDDEN);
    conv_w(img_proj_w, wip, (long long)HIDDEN * HIDDEN);
    conv_w(txt_proj_w, wtp, (long long)HIDDEN * HIDDEN);
    conv_w(img_mlp_w1, wim1, (long long)MLPD * HIDDEN);
    conv_w(img_mlp_w2, wim2, (long long)HIDDEN * MLPD);
    conv_w(txt_mlp_w1, wtm1, (long long)MLPD * HIDDEN);
    conv_w(txt_mlp_w2, wtm2, (long long)HIDDEN * MLPD);

    // ---- QKV for both streams ----
    ln_mod_kernel<<<T_IMG, 256>>>(img, img_mod1, xm16);
    launch_gemm(xm16, wiq, img_qkv_b, qkv_i, nullptr, T_IMG, 3 * HIDDEN, HIDDEN,
                HIDDEN, HIDDEN, 3 * HIDDEN, 0, 0, 0, 1, 1.0f, 0, 1, 0);
    ln_mod_kernel<<<T_TXT, 256>>>(txt, txt_mod1, xm16);
    launch_gemm(xm16, wtq, txt_qkv_b, qkv_t, nullptr, T_TXT, 3 * HIDDEN, HIDDEN,
                HIDDEN, HIDDEN, 3 * HIDDEN, 0, 0, 0, 1, 1.0f, 0, 1, 0);

    // ---- RMS norm + RoPE + scatter (txt tokens: l in [0,512), img [512,2048)) ----
    rmsrope_kernel<<<dim3(T_TXT, NUM_HEADS), HEAD_DIM>>>(qkv_t, txt_q_scale, txt_k_scale, pe, q16, k16, vT16, 0);
    rmsrope_kernel<<<dim3(T_IMG, NUM_HEADS), HEAD_DIM>>>(qkv_i, img_q_scale, img_k_scale, pe, q16, k16, vT16, T_TXT);

    // ---- Attention ----
    launch_gemm(q16, k16, nullptr, scores, nullptr, SEQ_L, SEQ_L, HEAD_DIM,
                HEAD_DIM, HEAD_DIM, SEQ_L,
                (long long)SEQ_L * HEAD_DIM, (long long)SEQ_L * HEAD_DIM,
                (long long)SEQ_L * SEQ_L, NUM_HEADS, attn_scale, 0, 1, 0);
    softmax_kernel<<<NUM_HEADS * SEQ_L, 256>>>(scores, probs16);
    launch_gemm(probs16, vT16, nullptr, nullptr, attn16, SEQ_L, HEAD_DIM, SEQ_L,
                SEQ_L, SEQ_L, HIDDEN,
                (long long)SEQ_L * SEQ_L, (long long)HEAD_DIM * SEQ_L,
                (long long)HEAD_DIM, NUM_HEADS, 1.0f, 0, 0, 1);

    // ---- Attention projections + gated residuals ----
    launch_gemm(attn16 + (size_t)T_TXT * HIDDEN, wip, img_proj_b, tmp, nullptr,
                T_IMG, HIDDEN, HIDDEN, HIDDEN, HIDDEN, HIDDEN, 0, 0, 0, 1, 1.0f, 0, 1, 0);
    residual_kernel<false><<<4096, 256>>>(img, tmp, img_mod1 + 2 * HIDDEN, out_img, T_IMG * HIDDEN);

    launch_gemm(attn16, wtp, txt_proj_b, tmp, nullptr,
                T_TXT, HIDDEN, HIDDEN, HIDDEN, HIDDEN, HIDDEN, 0, 0, 0, 1, 1.0f, 0, 1, 0);
    residual_kernel<false><<<2048, 256>>>(txt, tmp, txt_mod1 + 2 * HIDDEN, out_txt, T_TXT * HIDDEN);

    // ---- img MLP ----
    ln_mod_kernel<<<T_IMG, 256>>>(out_img, img_mod2, xm16);
    launch_gemm(xm16, wim1, img_mlp_b1, nullptr, h16, T_IMG, MLPD, HIDDEN,
                HIDDEN, HIDDEN, MLPD, 0, 0, 0, 1, 1.0f, 1, 0, 1);
    launch_gemm(h16, wim2, img_mlp_b2, tmp, nullptr, T_IMG, HIDDEN, MLPD,
                MLPD, MLPD, HIDDEN, 0, 0, 0, 1, 1.0f, 0, 1, 0);
    residual_kernel<false><<<4096, 256>>>(out_img, tmp, img_mod2 + 2 * HIDDEN, out_img, T_IMG * HIDDEN);

    // ---- txt MLP (final residual fused with clip) ----
    ln_mod_kernel<<<T_TXT, 256>>>(out_txt, txt_mod2, xm16);
    launch_gemm(xm16, wtm1, txt_mlp_b1, nullptr, h16, T_TXT, MLPD, HIDDEN,
                HIDDEN, HIDDEN, MLPD, 0, 0, 0, 1, 1.0f, 1, 0, 1);
    launch_gemm(h16, wtm2, txt_mlp_b2, tmp, nullptr, T_TXT, HIDDEN, MLPD,
                MLPD, MLPD, HIDDEN, 0, 0, 0, 1, 1.0f, 0, 1, 0);
    residual_kernel<true><<<2048, 256>>>(out_txt, tmp, txt_mod2 + 2 * HIDDEN, out_txt, T_TXT * HIDDEN);
}